// round 14
// baseline (speedup 1.0000x reference)
#include <cuda_runtime.h>
#include <cuda_bf16.h>
#include <math.h>

// ---------------------------------------------------------------------------
// GraphSAGE (mean -> max -> lstm aggr) + JumpingKnowledge bi-LSTM attention
// N=50000, K=16, C=128, JK_H=192
// Round 14: persistent aggregation-LSTM kernel. All 16 steps in ONE launch;
//   resident blocks loop over tiles, grid-wide barrier between steps.
//   hA ping-pong; cp.async.cg keeps cross-block reads L2-coherent.
//   Tile math identical to round 13 (3861 us, rel_err 3.5e-4).
// ---------------------------------------------------------------------------

#define N_NODES 50000
#define KDEG    16
#define CDIM    128
#define JKH     192
#define E_EDGES (N_NODES * KDEG)

// ------------------------- scratch (static device globals) ------------------
__device__ float g_aggT[N_NODES * CDIM];
__device__ float g_h1 [N_NODES * CDIM];
__device__ float g_h1T[N_NODES * CDIM];
__device__ float g_h2 [N_NODES * CDIM];
__device__ float g_h2T[N_NODES * CDIM];
__device__ float g_h3 [N_NODES * CDIM];
__device__ float g_h3T[N_NODES * CDIM];
__device__ float g_hA0[N_NODES * CDIM];
__device__ float g_hA1[N_NODES * CDIM];
__device__ float g_cA [N_NODES * CDIM];
__device__ float g_xw [N_NODES * 4 * CDIM];     // XW = h2 @ Wih_a^T
__device__ float g_fwd [3][N_NODES * JKH];
__device__ float g_fwdT[3][N_NODES * JKH];
__device__ float g_bwd [3][N_NODES * JKH];
__device__ float g_bwdT[3][N_NODES * JKH];
__device__ float g_cf [N_NODES * JKH];
__device__ float g_cb [N_NODES * JKH];
__device__ float g_xT [N_NODES * CDIM];
__device__ float g_wT [720896];
__device__ int   g_src32[E_EDGES];
__device__ int   g_is64;
__device__ unsigned g_bar;

// ------------------------- small helpers -------------------------------------
__device__ __forceinline__ unsigned cvt_tf32(float x)
{
    unsigned r;
    asm("cvt.rna.tf32.f32 %0, %1;" : "=r"(r) : "f"(x));
    return r;
}
__device__ __forceinline__ float tf32f(float x)
{
    return __uint_as_float(cvt_tf32(x));
}
__device__ __forceinline__ void mma_tf32(float* c,
                                         unsigned a0, unsigned a1,
                                         unsigned a2, unsigned a3,
                                         unsigned b0, unsigned b1)
{
    asm volatile(
        "mma.sync.aligned.m16n8k8.row.col.f32.tf32.tf32.f32 "
        "{%0,%1,%2,%3}, {%4,%5,%6,%7}, {%8,%9}, {%0,%1,%2,%3};\n"
        : "+f"(c[0]), "+f"(c[1]), "+f"(c[2]), "+f"(c[3])
        : "r"(a0), "r"(a1), "r"(a2), "r"(a3), "r"(b0), "r"(b1));
}
__device__ __forceinline__ float sigf(float x) { return 1.f / (1.f + expf(-x)); }

__device__ __forceinline__ unsigned s2u(const void* p)
{
    unsigned a;
    asm("{.reg .u64 t; cvta.to.shared.u64 t, %1; cvt.u32.u64 %0, t;}"
        : "=r"(a) : "l"(p));
    return a;
}
__device__ __forceinline__ void cp16(unsigned d, const void* s, int sz)
{
    asm volatile("cp.async.cg.shared.global [%0], [%1], 16, %2;\n"
                 :: "r"(d), "l"(s), "r"(sz));
}
#define CP_COMMIT() asm volatile("cp.async.commit_group;\n")
#define CP_WAIT0()  asm volatile("cp.async.wait_group 0;\n")

// ------------------------- dtype detect / convert ----------------------------
__global__ void detect_kernel(const void* __restrict__ p)
{
    const long long* a = (const long long*)p;
    int ok = 1;
    for (int i = 0; i < 256; ++i) {
        long long v = a[i];
        if (v < 0 || v >= N_NODES) { ok = 0; break; }
    }
    g_is64 = ok;
    g_bar = 0u;               // reset persistent-kernel barrier each launch
}
__global__ void s32_convert(const void* __restrict__ p, int* __restrict__ src32)
{
    int i = blockIdx.x * blockDim.x + threadIdx.x;
    if (i >= E_EDGES) return;
    if (g_is64) src32[i] = (int)((const long long*)p)[i];
    else        src32[i] = ((const int*)p)[i];
}
__global__ void cvt_arr(const float* __restrict__ in, float* __restrict__ out, int n)
{
    int i = blockIdx.x * blockDim.x + threadIdx.x;
    if (i < n) out[i] = tf32f(in[i]);
}

#define NCVT 12
struct CvtJobs {
    const float* in[NCVT];
    float*       out[NCVT];
    int          n[NCVT];
};
__global__ void cvt_multi(CvtJobs J)
{
    int j = blockIdx.y;
    int n = J.n[j];
    const float* in = J.in[j];
    float* out = J.out[j];
    for (int i = blockIdx.x * blockDim.x + threadIdx.x; i < n;
         i += gridDim.x * blockDim.x)
        out[i] = tf32f(in[i]);
}

// ------------------------- tiling constants -----------------------------------
#define BM 128
#define BN 64
#define BK 32
#define SA_STAGE (BM * 32)          // 4096 floats
#define SB_STAGE (BN * 32)          // 2048 floats

// swizzled accessors: 16B chunk (row, kf4) lives at row*32 + (kf4^(row&7))*4
__device__ __forceinline__ float lds_sw(const float* s, int r, int kc)
{
    return s[r * 32 + (((kc >> 2) ^ (r & 7)) << 2) + (kc & 3)];
}

// ------------------------- plain dual tf32 GEMM -------------------------------
// C[M,Nout] = A1@W1^T + A2@W2^T + b1 + b2 (+relu). All A/W pre-tf32.
// A1 row gather via gidx. A2 == nullptr -> segment dropped (Ktot = K1).
__global__ __launch_bounds__(256)
void gemm_tf32(int M, int Nout, int K1, int K2,
               const float* __restrict__ A1,
               const int* __restrict__ gidx, int gstride, int goff,
               const float* __restrict__ A2,
               const float* __restrict__ W1, const float* __restrict__ W2,
               const float* __restrict__ b1, const float* __restrict__ b2,
               float* __restrict__ Cout, float* __restrict__ CoutT, int act)
{
    __shared__ float smem_all[2 * SA_STAGE + 2 * SB_STAGE];

    const int tid  = threadIdx.x;
    const int lane = tid & 31;
    const int warp = tid >> 5;
    const int wm   = warp & 3;
    const int wn   = warp >> 2;
    const int mbase = blockIdx.y * BM;
    const int nbase = blockIdx.x * BN;
    const int lq = lane >> 2;
    const int lr = lane & 3;

    int rg[4];
    #pragma unroll
    for (int p = 0; p < 4; ++p) {
        int grow = mbase + ((tid + p * 256) >> 3);
        rg[p] = (grow < M) ? (gidx ? __ldg(&gidx[grow * gstride + goff]) : grow) : 0;
    }

    float acc[2][4][4];
    #pragma unroll
    for (int mt = 0; mt < 2; ++mt)
        #pragma unroll
        for (int nt = 0; nt < 4; ++nt)
            #pragma unroll
            for (int f = 0; f < 4; ++f) acc[mt][nt][f] = 0.f;

    const int Ktot = (A2 == nullptr) ? K1 : (K1 + K2);
    const int T = Ktot / BK;

    auto stage = [&](int t, int s) {
        int kt = t * BK;
        bool seg2 = (kt >= K1);
        const float* A = seg2 ? A2 : A1;
        const float* W = seg2 ? W2 : W1;
        int K    = seg2 ? K2 : K1;
        int kloc = seg2 ? kt - K1 : kt;
        float* sa = smem_all + s * SA_STAGE;
        float* sb = smem_all + 2 * SA_STAGE + s * SB_STAGE;
        #pragma unroll
        for (int p = 0; p < 4; ++p) {
            int lin = tid + p * 256;
            int row = lin >> 3, kf4 = lin & 7;
            int grow = mbase + row;
            bool ok = grow < M;
            int r = seg2 ? (ok ? grow : 0) : rg[p];
            unsigned d = s2u(sa + row * 32 + ((kf4 ^ (row & 7)) << 2));
            cp16(d, A + (size_t)r * K + kloc + kf4 * 4, ok ? 16 : 0);
        }
        #pragma unroll
        for (int p = 0; p < 2; ++p) {
            int lin = tid + p * 256;
            int n = lin >> 3, kf4 = lin & 7;
            unsigned d = s2u(sb + n * 32 + ((kf4 ^ (n & 7)) << 2));
            cp16(d, W + (size_t)(nbase + n) * K + kloc + kf4 * 4, 16);
        }
        CP_COMMIT();
    };

    stage(0, 0);

    for (int t = 0; t < T; ++t) {
        int cur = t & 1;
        CP_WAIT0();
        __syncthreads();
        if (t + 1 < T) stage(t + 1, cur ^ 1);

        const float* sa = smem_all + cur * SA_STAGE;
        const float* sb = smem_all + 2 * SA_STAGE + cur * SB_STAGE;
        #pragma unroll
        for (int ks = 0; ks < 4; ++ks) {
            const int kc = ks * 8 + lr;
            unsigned bfr[4][2];
            #pragma unroll
            for (int nt = 0; nt < 4; ++nt) {
                int n = wn * 32 + nt * 8 + lq;
                bfr[nt][0] = __float_as_uint(lds_sw(sb, n, kc));
                bfr[nt][1] = __float_as_uint(lds_sw(sb, n, kc + 4));
            }
            #pragma unroll
            for (int mt = 0; mt < 2; ++mt) {
                int r = wm * 32 + mt * 16 + lq;
                unsigned a0 = __float_as_uint(lds_sw(sa, r, kc));
                unsigned a1 = __float_as_uint(lds_sw(sa, r + 8, kc));
                unsigned a2 = __float_as_uint(lds_sw(sa, r, kc + 4));
                unsigned a3 = __float_as_uint(lds_sw(sa, r + 8, kc + 4));
                #pragma unroll
                for (int nt = 0; nt < 4; ++nt)
                    mma_tf32(acc[mt][nt], a0, a1, a2, a3, bfr[nt][0], bfr[nt][1]);
            }
        }
        __syncthreads();
    }

    #pragma unroll
    for (int mt = 0; mt < 2; ++mt) {
        #pragma unroll
        for (int nt = 0; nt < 4; ++nt) {
            int col  = nbase + wn * 32 + nt * 8 + 2 * lr;
            float bias0 = (b1 ? b1[col]     : 0.f) + (b2 ? b2[col]     : 0.f);
            float bias1 = (b1 ? b1[col + 1] : 0.f) + (b2 ? b2[col + 1] : 0.f);
            int row0 = mbase + wm * 32 + mt * 16 + lq;
            float v0 = acc[mt][nt][0] + bias0;
            float v1 = acc[mt][nt][1] + bias1;
            float v2 = acc[mt][nt][2] + bias0;
            float v3 = acc[mt][nt][3] + bias1;
            if (act) {
                v0 = fmaxf(v0, 0.f); v1 = fmaxf(v1, 0.f);
                v2 = fmaxf(v2, 0.f); v3 = fmaxf(v3, 0.f);
            }
            if (row0 < M) {
                size_t o = (size_t)row0 * Nout + col;
                Cout[o] = v0; Cout[o + 1] = v1;
                if (CoutT) { CoutT[o] = tf32f(v0); CoutT[o + 1] = tf32f(v1); }
            }
            if (row0 + 8 < M) {
                size_t o = (size_t)(row0 + 8) * Nout + col;
                Cout[o] = v2; Cout[o + 1] = v3;
                if (CoutT) { CoutT[o] = tf32f(v2); CoutT[o + 1] = tf32f(v3); }
            }
        }
    }
}

// ------------------------- persistent aggregation LSTM ------------------------
// All KDEG steps in one launch. Grid must be fully resident (host sizes it via
// the occupancy API). Step s reads hprev from ping-pong buffer (s&1 ? hbuf0 :
// hbuf1) via cp.async.cg (L2-coherent) and writes hout to the other buffer.
// z = XW[gidx[n*KDEG+step]] + h_prev@Whh^T + bias; fused gate update.
__global__ __launch_bounds__(256)
void lstm_agg_persist(int M, int H,
                      const float* __restrict__ XW,
                      const int* __restrict__ gidx,
                      const float* __restrict__ Whh,
                      const float* __restrict__ bih, const float* __restrict__ bhh,
                      float* __restrict__ cst,
                      float* __restrict__ hbuf0, float* __restrict__ hbuf1)
{
    __shared__ float smem_all[2 * SA_STAGE + 2 * SB_STAGE];

    const int tid  = threadIdx.x;
    const int lane = tid & 31;
    const int warp = tid >> 5;
    const int wm   = warp & 3;
    const int wn   = warp >> 2;
    const int lq = lane >> 2;
    const int lr = lane & 3;
    const int TX = H / 16;                       // column tiles
    const int NT = TX * ((M + BM - 1) / BM);     // total tiles per step

    for (int step = 0; step < KDEG; ++step) {
        const float* hprev = (step == 0) ? nullptr
                           : ((step & 1) ? hbuf0 : hbuf1);
        float* hout = (step & 1) ? hbuf1 : hbuf0;

        for (int tile = blockIdx.x; tile < NT; tile += gridDim.x) {
            const int cbase = (tile % TX) * 16;
            const int mbase = (tile / TX) * BM;

            float acc[2][4][4];
            #pragma unroll
            for (int mt = 0; mt < 2; ++mt)
                #pragma unroll
                for (int nt = 0; nt < 4; ++nt)
                    #pragma unroll
                    for (int f = 0; f < 4; ++f) acc[mt][nt][f] = 0.f;

            if (hprev) {
                const int T = H / BK;            // 4 k-tiles
                auto stage = [&](int t, int s) {
                    int kloc = t * BK;
                    float* sa = smem_all + s * SA_STAGE;
                    float* sb = smem_all + 2 * SA_STAGE + s * SB_STAGE;
                    #pragma unroll
                    for (int p = 0; p < 4; ++p) {
                        int lin = tid + p * 256;
                        int row = lin >> 3, kf4 = lin & 7;
                        int grow = mbase + row;
                        bool ok = grow < M;
                        int r = ok ? grow : 0;
                        unsigned d = s2u(sa + row * 32 + ((kf4 ^ (row & 7)) << 2));
                        cp16(d, hprev + (size_t)r * H + kloc + kf4 * 4, ok ? 16 : 0);
                    }
                    #pragma unroll
                    for (int p = 0; p < 2; ++p) {
                        int lin = tid + p * 256;
                        int n = lin >> 3, kf4 = lin & 7;
                        int wrow = (n >> 4) * H + cbase + (n & 15);
                        unsigned d = s2u(sb + n * 32 + ((kf4 ^ (n & 7)) << 2));
                        cp16(d, Whh + (size_t)wrow * H + kloc + kf4 * 4, 16);
                    }
                    CP_COMMIT();
                };

                stage(0, 0);
                for (int t = 0; t < T; ++t) {
                    int cur = t & 1;
                    CP_WAIT0();
                    __syncthreads();
                    if (t + 1 < T) stage(t + 1, cur ^ 1);

                    const float* sa = smem_all + cur * SA_STAGE;
                    const float* sb = smem_all + 2 * SA_STAGE + cur * SB_STAGE;
                    #pragma unroll
                    for (int ks = 0; ks < 4; ++ks) {
                        const int kc = ks * 8 + lr;
                        unsigned bfr[4][2];
                        #pragma unroll
                        for (int nt = 0; nt < 4; ++nt) {
                            int n = nt * 16 + wn * 8 + lq;
                            bfr[nt][0] = __float_as_uint(lds_sw(sb, n, kc));
                            bfr[nt][1] = __float_as_uint(lds_sw(sb, n, kc + 4));
                        }
                        #pragma unroll
                        for (int mt = 0; mt < 2; ++mt) {
                            int r = wm * 32 + mt * 16 + lq;
                            unsigned a0 = __float_as_uint(lds_sw(sa, r, kc));
                            unsigned a1 = __float_as_uint(lds_sw(sa, r + 8, kc));
                            unsigned a2 = __float_as_uint(lds_sw(sa, r, kc + 4));
                            unsigned a3 = __float_as_uint(lds_sw(sa, r + 8, kc + 4));
                            #pragma unroll
                            for (int nt = 0; nt < 4; ++nt)
                                mma_tf32(acc[mt][nt], a0, a1, a2, a3,
                                         bfr[nt][0], bfr[nt][1]);
                        }
                    }
                    __syncthreads();
                }
            }

            // ---- epilogue: XW gather + gate update ----
            const int cl0 = wn * 8 + 2 * lr;
            float bI[2], bF[2], bG[2], bO[2];
            #pragma unroll
            for (int cc = 0; cc < 2; ++cc) {
                int col = cbase + cl0 + cc;
                bI[cc] = bih[0 * H + col] + bhh[0 * H + col];
                bF[cc] = bih[1 * H + col] + bhh[1 * H + col];
                bG[cc] = bih[2 * H + col] + bhh[2 * H + col];
                bO[cc] = bih[3 * H + col] + bhh[3 * H + col];
            }

            #pragma unroll
            for (int mt = 0; mt < 2; ++mt) {
                int row0 = mbase + wm * 32 + mt * 16 + lq;
                #pragma unroll
                for (int p = 0; p < 2; ++p) {
                    int row = row0 + p * 8;
                    if (row >= M) continue;

                    int sr = __ldg(&gidx[row * KDEG + step]);
                    const float* xr = XW + (size_t)sr * (4 * H) + cbase + cl0;
                    float2 xw[4];
                    #pragma unroll
                    for (int g = 0; g < 4; ++g)
                        xw[g] = __ldg((const float2*)(xr + g * H));

                    #pragma unroll
                    for (int cc = 0; cc < 2; ++cc) {
                        int f = p * 2 + cc;
                        int col = cbase + cl0 + cc;
                        float zi = acc[mt][0][f] + bI[cc] + (cc ? xw[0].y : xw[0].x);
                        float zf = acc[mt][1][f] + bF[cc] + (cc ? xw[1].y : xw[1].x);
                        float zg = acc[mt][2][f] + bG[cc] + (cc ? xw[2].y : xw[2].x);
                        float zo = acc[mt][3][f] + bO[cc] + (cc ? xw[3].y : xw[3].x);
                        float ig = sigf(zi), fg = sigf(zf);
                        float gg = tanhf(zg), og = sigf(zo);
                        size_t idx = (size_t)row * H + col;
                        float cp = (step == 0) ? 0.f : cst[idx];
                        float cn = fg * cp + ig * gg;
                        cst[idx] = cn;
                        hout[idx] = tf32f(og * tanhf(cn));
                    }
                }
            }
        }

        // ---- grid-wide barrier between steps ----
        if (step + 1 < KDEG) {
            __syncthreads();
            if (tid == 0) {
                __threadfence();
                atomicAdd(&g_bar, 1u);
                unsigned target = (unsigned)gridDim.x * (unsigned)(step + 1);
                while (*(volatile unsigned*)&g_bar < target) { }
            }
            __syncthreads();
        }
    }
}

// ------------------------- fused LSTM-step GEMM (dual-chain, JK) --------------
__global__ __launch_bounds__(256)
void gemm_lstm_tf32(int M, int H, int K1,
                    const float* __restrict__ X0, const float* __restrict__ X1,
                    const float* __restrict__ hprev0, const float* __restrict__ hprev1,
                    const float* __restrict__ Wih0, const float* __restrict__ Whh0,
                    const float* __restrict__ bih0, const float* __restrict__ bhh0,
                    const float* __restrict__ Wih1, const float* __restrict__ Whh1,
                    const float* __restrict__ bih1, const float* __restrict__ bhh1,
                    float* __restrict__ cst0, float* __restrict__ cst1,
                    float* __restrict__ hout0, float* __restrict__ hout1,
                    float* __restrict__ houtT0, float* __restrict__ houtT1,
                    int zero_c)
{
    __shared__ float smem_all[2 * SA_STAGE + 2 * SB_STAGE];

    const int zsel = blockIdx.z;
    const float* X     = zsel ? X1     : X0;
    const float* hprev = zsel ? hprev1 : hprev0;
    const float* Wih   = zsel ? Wih1   : Wih0;
    const float* Whh   = zsel ? Whh1   : Whh0;
    const float* bih   = zsel ? bih1   : bih0;
    const float* bhh   = zsel ? bhh1   : bhh0;
    float* cst   = zsel ? cst1   : cst0;
    float* hout  = zsel ? hout1  : hout0;
    float* houtT = zsel ? houtT1 : houtT0;

    const int tid  = threadIdx.x;
    const int lane = tid & 31;
    const int warp = tid >> 5;
    const int wm   = warp & 3;
    const int wn   = warp >> 2;
    const int mbase = blockIdx.y * BM;
    const int cbase = blockIdx.x * 16;
    const int lq = lane >> 2;
    const int lr = lane & 3;

    float acc[2][4][4];
    #pragma unroll
    for (int mt = 0; mt < 2; ++mt)
        #pragma unroll
        for (int nt = 0; nt < 4; ++nt)
            #pragma unroll
            for (int f = 0; f < 4; ++f) acc[mt][nt][f] = 0.f;

    const int Ktot = K1 + ((hprev != nullptr) ? H : 0);
    const int T = Ktot / BK;

    auto stage = [&](int t, int s) {
        int kt = t * BK;
        bool seg2 = (kt >= K1);
        const float* A = seg2 ? hprev : X;
        const float* W = seg2 ? Whh : Wih;
        int K    = seg2 ? H : K1;
        int kloc = seg2 ? kt - K1 : kt;
        float* sa = smem_all + s * SA_STAGE;
        float* sb = smem_all + 2 * SA_STAGE + s * SB_STAGE;
        #pragma unroll
        for (int p = 0; p < 4; ++p) {
            int lin = tid + p * 256;
            int row = lin >> 3, kf4 = lin & 7;
            int grow = mbase + row;
            bool ok = grow < M;
            int r = ok ? grow : 0;
            unsigned d = s2u(sa + row * 32 + ((kf4 ^ (row & 7)) << 2));
            cp16(d, A + (size_t)r * K + kloc + kf4 * 4, ok ? 16 : 0);
        }
        #pragma unroll
        for (int p = 0; p < 2; ++p) {
            int lin = tid + p * 256;
            int n = lin >> 3, kf4 = lin & 7;
            int wrow = (n >> 4) * H + cbase + (n & 15);   // gate-major W rows
            unsigned d = s2u(sb + n * 32 + ((kf4 ^ (n & 7)) << 2));
            cp16(d, W + (size_t)wrow * K + kloc + kf4 * 4, 16);
        }
        CP_COMMIT();
    };

    stage(0, 0);

    for (int t = 0; t < T; ++t) {
        int cur = t & 1;
        CP_WAIT0();
        __syncthreads();
        if (t + 1 < T) stage(t + 1, cur ^ 1);

        const float* sa = smem_all + cur * SA_STAGE;
        const float* sb = smem_all + 2 * SA_STAGE + cur * SB_STAGE;
        #pragma unroll
        for (int ks = 0; ks < 4; ++ks) {
            const int kc = ks * 8 + lr;
            unsigned bfr[4][2];
            #pragma unroll
            for (int nt = 0; nt < 4; ++nt) {
                int n = nt * 16 + wn * 8 + lq;        // gate nt
                bfr[nt][0] = __float_as_uint(lds_sw(sb, n, kc));
                bfr[nt][1] = __float_as_uint(lds_sw(sb, n, kc + 4));
            }
            #pragma unroll
            for (int mt = 0; mt < 2; ++mt) {
                int r = wm * 32 + mt * 16 + lq;
                unsigned a0 = __float_as_uint(lds_sw(sa, r, kc));
                unsigned a1 = __float_as_uint(lds_sw(sa, r + 8, kc));
                unsigned a2 = __float_as_uint(lds_sw(sa, r, kc + 4));
                unsigned a3 = __float_as_uint(lds_sw(sa, r + 8, kc + 4));
                #pragma unroll
                for (int nt = 0; nt < 4; ++nt)
                    mma_tf32(acc[mt][nt], a0, a1, a2, a3, bfr[nt][0], bfr[nt][1]);
            }
        }
        __syncthreads();
    }

    const int cl0 = wn * 8 + 2 * lr;
    float bI[2], bF[2], bG[2], bO[2];
    #pragma unroll
    for (int cc = 0; cc < 2; ++cc) {
        int col = cbase + cl0 + cc;
        bI[cc] = bih[0 * H + col] + bhh[0 * H + col];
        bF[cc] = bih[1 * H + col] + bhh[1 * H + col];
        bG[cc] = bih[2 * H + col] + bhh[2 * H + col];
        bO[cc] = bih[3 * H + col] + bhh[3 * H + col];
    }

    #pragma unroll
    for (int mt = 0; mt < 2; ++mt) {
        int row0 = mbase + wm * 32 + mt * 16 + lq;
        #pragma unroll
        for (int p = 0; p < 2; ++p) {
            int row = row0 + p * 8;
            if (row >= M) continue;
            #pragma unroll
            for (int cc = 0; cc < 2; ++cc) {
                int f = p * 2 + cc;
                int col = cbase + cl0 + cc;
                float zi = acc[mt][0][f] + bI[cc];
                float zf = acc[mt][1][f] + bF[cc];
                float zg = acc[mt][2][f] + bG[cc];
                float zo = acc[mt][3][f] + bO[cc];
                float ig = sigf(zi), fg = sigf(zf);
                float gg = tanhf(zg), og = sigf(zo);
                size_t idx = (size_t)row * H + col;
                float cp = zero_c ? 0.f : cst[idx];
                float cn = fg * cp + ig * gg;
                float hv = og * tanhf(cn);
                cst[idx] = cn;
                if (hout) hout[idx] = hv;
                houtT[idx] = tf32f(hv);
            }
        }
    }
}

// ------------------------- aggregation kernels (tf32 outputs) -----------------
__global__ void agg_mean_kernel(const float* __restrict__ x,
                                const int* __restrict__ src,
                                float* __restrict__ outT)
{
    int n = blockIdx.x;
    int c = threadIdx.x;
    __shared__ int sidx[KDEG];
    if (c < KDEG) sidx[c] = src[n * KDEG + c];
    __syncthreads();
    float s = 0.f;
    #pragma unroll
    for (int k = 0; k < KDEG; ++k)
        s += x[(long long)sidx[k] * CDIM + c];
    outT[(long long)n * CDIM + c] = tf32f(s * (1.0f / (float)KDEG));
}

__global__ void agg_max_kernel(const float* __restrict__ x,
                               const int* __restrict__ src,
                               float* __restrict__ outT)
{
    int n = blockIdx.x;
    int c = threadIdx.x;
    __shared__ int sidx[KDEG];
    if (c < KDEG) sidx[c] = src[n * KDEG + c];
    __syncthreads();
    float m = -INFINITY;
    #pragma unroll
    for (int k = 0; k < KDEG; ++k)
        m = fmaxf(m, x[(long long)sidx[k] * CDIM + c]);
    outT[(long long)n * CDIM + c] = tf32f(m);
}

// ------------------------- JK attention + output ------------------------------
__global__ void jk_att_kernel(const float* __restrict__ h1,
                              const float* __restrict__ h2,
                              const float* __restrict__ h3,
                              const float* __restrict__ fwd0,
                              const float* __restrict__ fwd1,
                              const float* __restrict__ fwd2,
                              const float* __restrict__ bwd0,
                              const float* __restrict__ bwd1,
                              const float* __restrict__ bwd2,
                              const float* __restrict__ attw,
                              const float* __restrict__ attb,
                              float* __restrict__ out)
{
    int n = blockIdx.x;
    int tid = threadIdx.x;                 // 128
    const float* fw[3] = { fwd0, fwd1, fwd2 };
    const float* bw[3] = { bwd2, bwd1, bwd0 };   // bwd[::-1]

    __shared__ float red[128];
    __shared__ float sc[3];
    __shared__ float w[3];

    for (int t = 0; t < 3; ++t) {
        float p = 0.f;
        for (int j = tid; j < JKH; j += 128)
            p += fw[t][(long long)n * JKH + j] * attw[j]
               + bw[t][(long long)n * JKH + j] * attw[JKH + j];
        red[tid] = p;
        __syncthreads();
        for (int s = 64; s > 0; s >>= 1) {
            if (tid < s) red[tid] += red[tid + s];
            __syncthreads();
        }
        if (tid == 0) sc[t] = red[0] + attb[0];
        __syncthreads();
    }
    if (tid == 0) {
        float m = fmaxf(sc[0], fmaxf(sc[1], sc[2]));
        float e0 = expf(sc[0] - m), e1 = expf(sc[1] - m), e2 = expf(sc[2] - m);
        float s = e0 + e1 + e2;
        w[0] = e0 / s; w[1] = e1 / s; w[2] = e2 / s;
    }
    __syncthreads();
    long long o = (long long)n * CDIM + tid;
    out[o] = w[0] * h1[o] + w[1] * h2[o] + w[2] * h3[o];
}

// ------------------------- host driver ----------------------------------------
static void launch_gemm(int M, int Nout, int K1, int K2,
                        const float* A1, const int* gidx, int gstride, int goff,
                        const float* A2,
                        const float* W1, const float* W2,
                        const float* b1, const float* b2,
                        float* C, float* CT, int act)
{
    dim3 grid(Nout / BN, (M + BM - 1) / BM);
    gemm_tf32<<<grid, 256>>>(M, Nout, K1, K2, A1, gidx, gstride, goff,
                             A2, W1, W2, b1, b2, C, CT, act);
}

static void launch_lstm_step2(int M, int H, int K1,
                              const float* X0, const float* hp0,
                              const float* Wih0, const float* Whh0,
                              const float* bih0, const float* bhh0,
                              float* c0, float* ho0, float* hoT0,
                              const float* X1, const float* hp1,
                              const float* Wih1, const float* Whh1,
                              const float* bih1, const float* bhh1,
                              float* c1, float* ho1, float* hoT1,
                              int zero_c)
{
    dim3 grid(H / 16, (M + BM - 1) / BM, 2);
    gemm_lstm_tf32<<<grid, 256>>>(M, H, K1,
                                  X0, X1,
                                  hp0, hp1,
                                  Wih0, Whh0, bih0, bhh0,
                                  Wih1, Whh1, bih1, bhh1,
                                  c0, c1, ho0, ho1, hoT0, hoT1, zero_c);
}

extern "C" void kernel_launch(void* const* d_in, const int* in_sizes, int n_in,
                              void* d_out, int out_size)
{
    int epos = -1;
    for (int i = 0; i < n_in; ++i)
        if (in_sizes[i] == 2 * E_EDGES) { epos = i; break; }

    const float* P[24];
    int q = 0;
    for (int i = 0; i < n_in && q < 24; ++i) {
        if (i == epos) continue;
        P[q++] = (const float*)d_in[i];
    }
    const float* x     = P[0];
    const float* Wl1   = P[1];  const float* bl1  = P[2];  const float* Wr1 = P[3];
    const float* Wl2   = P[4];  const float* bl2  = P[5];  const float* Wr2 = P[6];
    const float* Wl3   = P[7];  const float* bl3  = P[8];  const float* Wr3 = P[9];
    const float* Wih_a = P[10]; const float* Whh_a = P[11];
    const float* bih_a = P[12]; const float* bhh_a = P[13];
    const float* Wih_f = P[14]; const float* Whh_f = P[15];
    const float* bih_f = P[16]; const float* bhh_f = P[17];
    const float* Wih_b = P[18]; const float* Whh_b = P[19];
    const float* bih_b = P[20]; const float* bhh_b = P[21];
    const float* att_w = P[22]; const float* att_b = P[23];
    const void* edge_raw = d_in[epos];

    float *aggT, *h1, *h1T, *h2, *h2T, *h3, *h3T, *hA0, *hA1, *cA, *xw;
    float *fwd, *fwdT, *bwd, *bwdT, *cf, *cb, *xT, *wT;
    int* src;
    cudaGetSymbolAddress((void**)&aggT, g_aggT);
    cudaGetSymbolAddress((void**)&h1,  g_h1);
    cudaGetSymbolAddress((void**)&h1T, g_h1T);
    cudaGetSymbolAddress((void**)&h2,  g_h2);
    cudaGetSymbolAddress((void**)&h2T, g_h2T);
    cudaGetSymbolAddress((void**)&h3,  g_h3);
    cudaGetSymbolAddress((void**)&h3T, g_h3T);
    cudaGetSymbolAddress((void**)&hA0, g_hA0);
    cudaGetSymbolAddress((void**)&hA1, g_hA1);
    cudaGetSymbolAddress((void**)&cA,  g_cA);
    cudaGetSymbolAddress((void**)&xw,  g_xw);
    cudaGetSymbolAddress((void**)&fwd,  g_fwd);
    cudaGetSymbolAddress((void**)&fwdT, g_fwdT);
    cudaGetSymbolAddress((void**)&bwd,  g_bwd);
    cudaGetSymbolAddress((void**)&bwdT, g_bwdT);
    cudaGetSymbolAddress((void**)&cf,  g_cf);
    cudaGetSymbolAddress((void**)&cb,  g_cb);
    cudaGetSymbolAddress((void**)&xT,  g_xT);
    cudaGetSymbolAddress((void**)&wT,  g_wT);
    cudaGetSymbolAddress((void**)&src, g_src32);

    // weight scratch offsets (tf32 copies)
    float* Wl1T  = wT;            float* Wr1T  = wT + 16384;
    float* Wl2T  = wT + 32768;    float* Wr2T  = wT + 49152;
    float* Wl3T  = wT + 65536;    float* Wr3T  = wT + 81920;
    float* WihaT = wT + 98304;    float* WhhaT = wT + 163840;
    float* WihfT = wT + 229376;   float* WhhfT = wT + 327680;
    float* WihbT = wT + 475136;   float* WhhbT = wT + 573440;

    float* out = (float*)d_out;
    const int N = N_NODES;

    // persistent-kernel grid: fully resident by construction
    int nsm = 148, nbper = 0;
    cudaDeviceGetAttribute(&nsm, cudaDevAttrMultiProcessorCount, 0);
    cudaOccupancyMaxActiveBlocksPerMultiprocessor(&nbper, lstm_agg_persist, 256, 0);
    if (nbper < 1) nbper = 1;
    int NBLK = nsm * nbper;

    // ---- one-shot conversions ----
    detect_kernel<<<1, 1>>>(edge_raw);
    s32_convert<<<(E_EDGES + 255) / 256, 256>>>(edge_raw, src);
    cvt_arr<<<(N * CDIM + 255) / 256, 256>>>(x, xT, N * CDIM);
    {
        CvtJobs J;
        const float* ins[NCVT]  = { Wl1, Wr1, Wl2, Wr2, Wl3, Wr3,
                                    Wih_a, Whh_a, Wih_f, Whh_f, Wih_b, Whh_b };
        float* outs[NCVT] = { Wl1T, Wr1T, Wl2T, Wr2T, Wl3T, Wr3T,
                              WihaT, WhhaT, WihfT, WhhfT, WihbT, WhhbT };
        int ns[NCVT] = { 16384, 16384, 16384, 16384, 16384, 16384,
                         4 * CDIM * CDIM, 4 * CDIM * CDIM,
                         4 * JKH * CDIM, 4 * JKH * JKH,
                         4 * JKH * CDIM, 4 * JKH * JKH };
        for (int j = 0; j < NCVT; ++j) { J.in[j] = ins[j]; J.out[j] = outs[j]; J.n[j] = ns[j]; }
        dim3 g(576, NCVT);
        cvt_multi<<<g, 256>>>(J);
    }

    // ---- layer 1: mean agg + linear + relu ----
    agg_mean_kernel<<<N, CDIM>>>(x, src, aggT);
    launch_gemm(N, CDIM, CDIM, CDIM, aggT, nullptr, 0, 0, xT,
                Wl1T, Wr1T, bl1, nullptr, h1, h1T, 1);

    // ---- layer 2: max agg + linear + relu ----
    agg_max_kernel<<<N, CDIM>>>(h1, src, aggT);
    launch_gemm(N, CDIM, CDIM, CDIM, aggT, nullptr, 0, 0, h1T,
                Wl2T, Wr2T, bl2, nullptr, h2, h2T, 1);

    // ---- layer 3: LSTM aggregation (persistent, all 16 steps) ----
    launch_gemm(N, 4 * CDIM, CDIM, 0, h2T, nullptr, 0, 0, nullptr,
                WihaT, nullptr, nullptr, nullptr, xw, nullptr, 0);
    lstm_agg_persist<<<NBLK, 256>>>(N, CDIM, xw, src, WhhaT, bih_a, bhh_a,
                                    cA, hA0, hA1);
    // final h is in hA1 (step 15 is odd)
    launch_gemm(N, CDIM, CDIM, CDIM, hA1, nullptr, 0, 0, h2T,
                Wl3T, Wr3T, bl3, nullptr, h3, h3T, 0);

    // ---- JumpingKnowledge bi-LSTM: fwd+bwd merged per step ----
    {
        const float* hsT[3] = { h1T, h2T, h3T };
        const float* hpF = nullptr;
        const float* hpB = nullptr;
        for (int t = 0; t < 3; ++t) {
            float* hoF  = fwd  + (size_t)t * N * JKH;
            float* hoFT = fwdT + (size_t)t * N * JKH;
            float* hoB  = bwd  + (size_t)t * N * JKH;
            float* hoBT = bwdT + (size_t)t * N * JKH;
            launch_lstm_step2(N, JKH, CDIM,
                              hsT[t],     hpF, WihfT, WhhfT, bih_f, bhh_f,
                              cf, hoF, hoFT,
                              hsT[2 - t], hpB, WihbT, WhhbT, bih_b, bhh_b,
                              cb, hoB, hoBT,
                              t == 0);
            hpF = hoFT;
            hpB = hoBT;
        }
        jk_att_kernel<<<N, CDIM>>>(h1, h2, h3,
                                   fwd, fwd + (size_t)N * JKH, fwd + (size_t)2 * N * JKH,
                                   bwd, bwd + (size_t)N * JKH, bwd + (size_t)2 * N * JKH,
                                   att_w, att_b, out);
    }
}

// round 15
// speedup vs baseline: 1.0606x; 1.0606x over previous
#include <cuda_runtime.h>
#include <cuda_bf16.h>
#include <math.h>

// ---------------------------------------------------------------------------
// GraphSAGE (mean -> max -> lstm aggr) + JumpingKnowledge bi-LSTM attention
// N=50000, K=16, C=128, JK_H=192
// Round 15: revert persistent kernel (neutral); MUFU-based fast activations
//   in LSTM epilogues (sigmoid/tanh via __expf+__fdividef, ~2ulp).
//   Structure otherwise identical to round 13 (3861 us).
// ---------------------------------------------------------------------------

#define N_NODES 50000
#define KDEG    16
#define CDIM    128
#define JKH     192
#define E_EDGES (N_NODES * KDEG)

// ------------------------- scratch (static device globals) ------------------
__device__ float g_aggT[N_NODES * CDIM];
__device__ float g_h1 [N_NODES * CDIM];
__device__ float g_h1T[N_NODES * CDIM];
__device__ float g_h2 [N_NODES * CDIM];
__device__ float g_h2T[N_NODES * CDIM];
__device__ float g_h3 [N_NODES * CDIM];
__device__ float g_h3T[N_NODES * CDIM];
__device__ float g_hAT[N_NODES * CDIM];
__device__ float g_cA [N_NODES * CDIM];
__device__ float g_xw [N_NODES * 4 * CDIM];     // XW = h2 @ Wih_a^T
__device__ float g_fwd [3][N_NODES * JKH];
__device__ float g_fwdT[3][N_NODES * JKH];
__device__ float g_bwd [3][N_NODES * JKH];
__device__ float g_bwdT[3][N_NODES * JKH];
__device__ float g_cf [N_NODES * JKH];
__device__ float g_cb [N_NODES * JKH];
__device__ float g_xT [N_NODES * CDIM];
__device__ float g_wT [720896];
__device__ int   g_src32[E_EDGES];
__device__ int   g_is64;

// ------------------------- small helpers -------------------------------------
__device__ __forceinline__ unsigned cvt_tf32(float x)
{
    unsigned r;
    asm("cvt.rna.tf32.f32 %0, %1;" : "=r"(r) : "f"(x));
    return r;
}
__device__ __forceinline__ float tf32f(float x)
{
    return __uint_as_float(cvt_tf32(x));
}
__device__ __forceinline__ void mma_tf32(float* c,
                                         unsigned a0, unsigned a1,
                                         unsigned a2, unsigned a3,
                                         unsigned b0, unsigned b1)
{
    asm volatile(
        "mma.sync.aligned.m16n8k8.row.col.f32.tf32.tf32.f32 "
        "{%0,%1,%2,%3}, {%4,%5,%6,%7}, {%8,%9}, {%0,%1,%2,%3};\n"
        : "+f"(c[0]), "+f"(c[1]), "+f"(c[2]), "+f"(c[3])
        : "r"(a0), "r"(a1), "r"(a2), "r"(a3), "r"(b0), "r"(b1));
}
// Fast activations: MUFU EX2/RCP based, ~2 ulp (1e-6 rel) — negligible vs the
// 3.5e-4 tf32 error floor. Correct saturation at +-inf.
__device__ __forceinline__ float sigf(float x)
{
    return __fdividef(1.f, 1.f + __expf(-x));
}
__device__ __forceinline__ float tanhff(float x)
{
    return __fdividef(2.f, 1.f + __expf(-2.f * x)) - 1.f;
}

__device__ __forceinline__ unsigned s2u(const void* p)
{
    unsigned a;
    asm("{.reg .u64 t; cvta.to.shared.u64 t, %1; cvt.u32.u64 %0, t;}"
        : "=r"(a) : "l"(p));
    return a;
}
__device__ __forceinline__ void cp16(unsigned d, const void* s, int sz)
{
    asm volatile("cp.async.cg.shared.global [%0], [%1], 16, %2;\n"
                 :: "r"(d), "l"(s), "r"(sz));
}
#define CP_COMMIT() asm volatile("cp.async.commit_group;\n")
#define CP_WAIT0()  asm volatile("cp.async.wait_group 0;\n")

// ------------------------- dtype detect / convert ----------------------------
__global__ void detect_kernel(const void* __restrict__ p)
{
    const long long* a = (const long long*)p;
    int ok = 1;
    for (int i = 0; i < 256; ++i) {
        long long v = a[i];
        if (v < 0 || v >= N_NODES) { ok = 0; break; }
    }
    g_is64 = ok;
}
__global__ void s32_convert(const void* __restrict__ p, int* __restrict__ src32)
{
    int i = blockIdx.x * blockDim.x + threadIdx.x;
    if (i >= E_EDGES) return;
    if (g_is64) src32[i] = (int)((const long long*)p)[i];
    else        src32[i] = ((const int*)p)[i];
}
__global__ void cvt_arr(const float* __restrict__ in, float* __restrict__ out, int n)
{
    int i = blockIdx.x * blockDim.x + threadIdx.x;
    if (i < n) out[i] = tf32f(in[i]);
}

#define NCVT 12
struct CvtJobs {
    const float* in[NCVT];
    float*       out[NCVT];
    int          n[NCVT];
};
__global__ void cvt_multi(CvtJobs J)
{
    int j = blockIdx.y;
    int n = J.n[j];
    const float* in = J.in[j];
    float* out = J.out[j];
    for (int i = blockIdx.x * blockDim.x + threadIdx.x; i < n;
         i += gridDim.x * blockDim.x)
        out[i] = tf32f(in[i]);
}

// ------------------------- tiling constants -----------------------------------
#define BM 128
#define BN 64
#define BK 32
#define SA_STAGE (BM * 32)          // 4096 floats
#define SB_STAGE (BN * 32)          // 2048 floats

// swizzled accessors: 16B chunk (row, kf4) lives at row*32 + (kf4^(row&7))*4
__device__ __forceinline__ float lds_sw(const float* s, int r, int kc)
{
    return s[r * 32 + (((kc >> 2) ^ (r & 7)) << 2) + (kc & 3)];
}

// ------------------------- plain dual tf32 GEMM -------------------------------
// C[M,Nout] = A1@W1^T + A2@W2^T + b1 + b2 (+relu). All A/W pre-tf32.
// A1 row gather via gidx. A2 == nullptr -> segment dropped (Ktot = K1).
__global__ __launch_bounds__(256)
void gemm_tf32(int M, int Nout, int K1, int K2,
               const float* __restrict__ A1,
               const int* __restrict__ gidx, int gstride, int goff,
               const float* __restrict__ A2,
               const float* __restrict__ W1, const float* __restrict__ W2,
               const float* __restrict__ b1, const float* __restrict__ b2,
               float* __restrict__ Cout, float* __restrict__ CoutT, int act)
{
    __shared__ float smem_all[2 * SA_STAGE + 2 * SB_STAGE];

    const int tid  = threadIdx.x;
    const int lane = tid & 31;
    const int warp = tid >> 5;
    const int wm   = warp & 3;
    const int wn   = warp >> 2;
    const int mbase = blockIdx.y * BM;
    const int nbase = blockIdx.x * BN;
    const int lq = lane >> 2;
    const int lr = lane & 3;

    int rg[4];
    #pragma unroll
    for (int p = 0; p < 4; ++p) {
        int grow = mbase + ((tid + p * 256) >> 3);
        rg[p] = (grow < M) ? (gidx ? __ldg(&gidx[grow * gstride + goff]) : grow) : 0;
    }

    float acc[2][4][4];
    #pragma unroll
    for (int mt = 0; mt < 2; ++mt)
        #pragma unroll
        for (int nt = 0; nt < 4; ++nt)
            #pragma unroll
            for (int f = 0; f < 4; ++f) acc[mt][nt][f] = 0.f;

    const int Ktot = (A2 == nullptr) ? K1 : (K1 + K2);
    const int T = Ktot / BK;

    auto stage = [&](int t, int s) {
        int kt = t * BK;
        bool seg2 = (kt >= K1);
        const float* A = seg2 ? A2 : A1;
        const float* W = seg2 ? W2 : W1;
        int K    = seg2 ? K2 : K1;
        int kloc = seg2 ? kt - K1 : kt;
        float* sa = smem_all + s * SA_STAGE;
        float* sb = smem_all + 2 * SA_STAGE + s * SB_STAGE;
        #pragma unroll
        for (int p = 0; p < 4; ++p) {
            int lin = tid + p * 256;
            int row = lin >> 3, kf4 = lin & 7;
            int grow = mbase + row;
            bool ok = grow < M;
            int r = seg2 ? (ok ? grow : 0) : rg[p];
            unsigned d = s2u(sa + row * 32 + ((kf4 ^ (row & 7)) << 2));
            cp16(d, A + (size_t)r * K + kloc + kf4 * 4, ok ? 16 : 0);
        }
        #pragma unroll
        for (int p = 0; p < 2; ++p) {
            int lin = tid + p * 256;
            int n = lin >> 3, kf4 = lin & 7;
            unsigned d = s2u(sb + n * 32 + ((kf4 ^ (n & 7)) << 2));
            cp16(d, W + (size_t)(nbase + n) * K + kloc + kf4 * 4, 16);
        }
        CP_COMMIT();
    };

    stage(0, 0);

    for (int t = 0; t < T; ++t) {
        int cur = t & 1;
        CP_WAIT0();
        __syncthreads();
        if (t + 1 < T) stage(t + 1, cur ^ 1);

        const float* sa = smem_all + cur * SA_STAGE;
        const float* sb = smem_all + 2 * SA_STAGE + cur * SB_STAGE;
        #pragma unroll
        for (int ks = 0; ks < 4; ++ks) {
            const int kc = ks * 8 + lr;
            unsigned bfr[4][2];
            #pragma unroll
            for (int nt = 0; nt < 4; ++nt) {
                int n = wn * 32 + nt * 8 + lq;
                bfr[nt][0] = __float_as_uint(lds_sw(sb, n, kc));
                bfr[nt][1] = __float_as_uint(lds_sw(sb, n, kc + 4));
            }
            #pragma unroll
            for (int mt = 0; mt < 2; ++mt) {
                int r = wm * 32 + mt * 16 + lq;
                unsigned a0 = __float_as_uint(lds_sw(sa, r, kc));
                unsigned a1 = __float_as_uint(lds_sw(sa, r + 8, kc));
                unsigned a2 = __float_as_uint(lds_sw(sa, r, kc + 4));
                unsigned a3 = __float_as_uint(lds_sw(sa, r + 8, kc + 4));
                #pragma unroll
                for (int nt = 0; nt < 4; ++nt)
                    mma_tf32(acc[mt][nt], a0, a1, a2, a3, bfr[nt][0], bfr[nt][1]);
            }
        }
        __syncthreads();
    }

    #pragma unroll
    for (int mt = 0; mt < 2; ++mt) {
        #pragma unroll
        for (int nt = 0; nt < 4; ++nt) {
            int col  = nbase + wn * 32 + nt * 8 + 2 * lr;
            float bias0 = (b1 ? b1[col]     : 0.f) + (b2 ? b2[col]     : 0.f);
            float bias1 = (b1 ? b1[col + 1] : 0.f) + (b2 ? b2[col + 1] : 0.f);
            int row0 = mbase + wm * 32 + mt * 16 + lq;
            float v0 = acc[mt][nt][0] + bias0;
            float v1 = acc[mt][nt][1] + bias1;
            float v2 = acc[mt][nt][2] + bias0;
            float v3 = acc[mt][nt][3] + bias1;
            if (act) {
                v0 = fmaxf(v0, 0.f); v1 = fmaxf(v1, 0.f);
                v2 = fmaxf(v2, 0.f); v3 = fmaxf(v3, 0.f);
            }
            if (row0 < M) {
                size_t o = (size_t)row0 * Nout + col;
                Cout[o] = v0; Cout[o + 1] = v1;
                if (CoutT) { CoutT[o] = tf32f(v0); CoutT[o + 1] = tf32f(v1); }
            }
            if (row0 + 8 < M) {
                size_t o = (size_t)(row0 + 8) * Nout + col;
                Cout[o] = v2; Cout[o + 1] = v3;
                if (CoutT) { CoutT[o] = tf32f(v2); CoutT[o + 1] = tf32f(v3); }
            }
        }
    }
}

// ------------------------- fused LSTM-step GEMM (dual-chain + XW) -------------
// One LSTM time step; blockIdx.z selects parameter set 0 or 1.
// If XW != nullptr: z = XW[gidx[n*gstride+goff]] + h_prev@Whh^T + bias
//   (x-part precomputed; only the recurrent K=H GEMM runs).
// Else: z = [x_t ; h_prev] @ [Wih ; Whh]^T + bias (original path).
// hprev == nullptr -> first step (no recurrent segment, c := 0).
__global__ __launch_bounds__(256)
void gemm_lstm_tf32(int M, int H, int K1,
                    const float* __restrict__ X0, const float* __restrict__ X1,
                    const float* __restrict__ XW0, const float* __restrict__ XW1,
                    const int* __restrict__ gidx, int gstride, int goff,
                    const float* __restrict__ hprev0, const float* __restrict__ hprev1,
                    const float* __restrict__ Wih0, const float* __restrict__ Whh0,
                    const float* __restrict__ bih0, const float* __restrict__ bhh0,
                    const float* __restrict__ Wih1, const float* __restrict__ Whh1,
                    const float* __restrict__ bih1, const float* __restrict__ bhh1,
                    float* __restrict__ cst0, float* __restrict__ cst1,
                    float* __restrict__ hout0, float* __restrict__ hout1,
                    float* __restrict__ houtT0, float* __restrict__ houtT1,
                    int zero_c)
{
    __shared__ float smem_all[2 * SA_STAGE + 2 * SB_STAGE];

    const int zsel = blockIdx.z;
    const float* X     = zsel ? X1     : X0;
    const float* XW    = zsel ? XW1    : XW0;
    const float* hprev = zsel ? hprev1 : hprev0;
    const float* Wih   = zsel ? Wih1   : Wih0;
    const float* Whh   = zsel ? Whh1   : Whh0;
    const float* bih   = zsel ? bih1   : bih0;
    const float* bhh   = zsel ? bhh1   : bhh0;
    float* cst   = zsel ? cst1   : cst0;
    float* hout  = zsel ? hout1  : hout0;
    float* houtT = zsel ? houtT1 : houtT0;

    const int tid  = threadIdx.x;
    const int lane = tid & 31;
    const int warp = tid >> 5;
    const int wm   = warp & 3;
    const int wn   = warp >> 2;
    const int mbase = blockIdx.y * BM;
    const int cbase = blockIdx.x * 16;
    const int lq = lane >> 2;
    const int lr = lane & 3;

    const bool use_xw = (XW != nullptr);
    const int KX = use_xw ? 0 : K1;        // x-segment length inside the GEMM

    int rg[4];
    if (!use_xw) {
        #pragma unroll
        for (int p = 0; p < 4; ++p) {
            int grow = mbase + ((tid + p * 256) >> 3);
            rg[p] = (grow < M) ? (gidx ? __ldg(&gidx[grow * gstride + goff]) : grow) : 0;
        }
    }

    float acc[2][4][4];
    #pragma unroll
    for (int mt = 0; mt < 2; ++mt)
        #pragma unroll
        for (int nt = 0; nt < 4; ++nt)
            #pragma unroll
            for (int f = 0; f < 4; ++f) acc[mt][nt][f] = 0.f;

    const int Ktot = KX + ((hprev != nullptr) ? H : 0);
    const int T = Ktot / BK;

    auto stage = [&](int t, int s) {
        int kt = t * BK;
        bool seg2 = (kt >= KX);
        const float* A = seg2 ? hprev : X;
        const float* W = seg2 ? Whh : Wih;
        int K    = seg2 ? H : K1;
        int kloc = seg2 ? kt - KX : kt;
        float* sa = smem_all + s * SA_STAGE;
        float* sb = smem_all + 2 * SA_STAGE + s * SB_STAGE;
        #pragma unroll
        for (int p = 0; p < 4; ++p) {
            int lin = tid + p * 256;
            int row = lin >> 3, kf4 = lin & 7;
            int grow = mbase + row;
            bool ok = grow < M;
            int r = seg2 ? (ok ? grow : 0) : rg[p];
            unsigned d = s2u(sa + row * 32 + ((kf4 ^ (row & 7)) << 2));
            cp16(d, A + (size_t)r * K + kloc + kf4 * 4, ok ? 16 : 0);
        }
        #pragma unroll
        for (int p = 0; p < 2; ++p) {
            int lin = tid + p * 256;
            int n = lin >> 3, kf4 = lin & 7;
            int wrow = (n >> 4) * H + cbase + (n & 15);   // gate-major W rows
            unsigned d = s2u(sb + n * 32 + ((kf4 ^ (n & 7)) << 2));
            cp16(d, W + (size_t)wrow * K + kloc + kf4 * 4, 16);
        }
        CP_COMMIT();
    };

    if (T > 0) stage(0, 0);

    for (int t = 0; t < T; ++t) {
        int cur = t & 1;
        CP_WAIT0();
        __syncthreads();
        if (t + 1 < T) stage(t + 1, cur ^ 1);

        const float* sa = smem_all + cur * SA_STAGE;
        const float* sb = smem_all + 2 * SA_STAGE + cur * SB_STAGE;
        #pragma unroll
        for (int ks = 0; ks < 4; ++ks) {
            const int kc = ks * 8 + lr;
            unsigned bfr[4][2];
            #pragma unroll
            for (int nt = 0; nt < 4; ++nt) {
                int n = nt * 16 + wn * 8 + lq;        // gate nt
                bfr[nt][0] = __float_as_uint(lds_sw(sb, n, kc));
                bfr[nt][1] = __float_as_uint(lds_sw(sb, n, kc + 4));
            }
            #pragma unroll
            for (int mt = 0; mt < 2; ++mt) {
                int r = wm * 32 + mt * 16 + lq;
                unsigned a0 = __float_as_uint(lds_sw(sa, r, kc));
                unsigned a1 = __float_as_uint(lds_sw(sa, r + 8, kc));
                unsigned a2 = __float_as_uint(lds_sw(sa, r, kc + 4));
                unsigned a3 = __float_as_uint(lds_sw(sa, r + 8, kc + 4));
                #pragma unroll
                for (int nt = 0; nt < 4; ++nt)
                    mma_tf32(acc[mt][nt], a0, a1, a2, a3, bfr[nt][0], bfr[nt][1]);
            }
        }
        __syncthreads();
    }

    // ---- fused LSTM epilogue (+ optional XW gather) ----
    const int cl0 = wn * 8 + 2 * lr;
    float bI[2], bF[2], bG[2], bO[2];
    #pragma unroll
    for (int cc = 0; cc < 2; ++cc) {
        int col = cbase + cl0 + cc;
        bI[cc] = bih[0 * H + col] + bhh[0 * H + col];
        bF[cc] = bih[1 * H + col] + bhh[1 * H + col];
        bG[cc] = bih[2 * H + col] + bhh[2 * H + col];
        bO[cc] = bih[3 * H + col] + bhh[3 * H + col];
    }

    #pragma unroll
    for (int mt = 0; mt < 2; ++mt) {
        int row0 = mbase + wm * 32 + mt * 16 + lq;
        #pragma unroll
        for (int p = 0; p < 2; ++p) {
            int row = row0 + p * 8;
            if (row >= M) continue;

            float2 xw[4];
            #pragma unroll
            for (int g = 0; g < 4; ++g) xw[g] = make_float2(0.f, 0.f);
            if (use_xw) {
                int sr = __ldg(&gidx[row * gstride + goff]);
                const float* xr = XW + (size_t)sr * (4 * H) + cbase + cl0;
                #pragma unroll
                for (int g = 0; g < 4; ++g)
                    xw[g] = __ldg((const float2*)(xr + g * H));
            }

            #pragma unroll
            for (int cc = 0; cc < 2; ++cc) {
                int f = p * 2 + cc;
                int col = cbase + cl0 + cc;
                float x0 = cc ? xw[0].y : xw[0].x;
                float x1 = cc ? xw[1].y : xw[1].x;
                float x2 = cc ? xw[2].y : xw[2].x;
                float x3 = cc ? xw[3].y : xw[3].x;
                float zi = acc[mt][0][f] + bI[cc] + x0;
                float zf = acc[mt][1][f] + bF[cc] + x1;
                float zg = acc[mt][2][f] + bG[cc] + x2;
                float zo = acc[mt][3][f] + bO[cc] + x3;
                float ig = sigf(zi), fg = sigf(zf);
                float gg = tanhff(zg), og = sigf(zo);
                size_t idx = (size_t)row * H + col;
                float cp = zero_c ? 0.f : cst[idx];
                float cn = fg * cp + ig * gg;
                float hv = og * tanhff(cn);
                cst[idx] = cn;
                if (hout) hout[idx] = hv;
                houtT[idx] = tf32f(hv);
            }
        }
    }
}

// ------------------------- aggregation kernels (tf32 outputs) -----------------
__global__ void agg_mean_kernel(const float* __restrict__ x,
                                const int* __restrict__ src,
                                float* __restrict__ outT)
{
    int n = blockIdx.x;
    int c = threadIdx.x;
    __shared__ int sidx[KDEG];
    if (c < KDEG) sidx[c] = src[n * KDEG + c];
    __syncthreads();
    float s = 0.f;
    #pragma unroll
    for (int k = 0; k < KDEG; ++k)
        s += x[(long long)sidx[k] * CDIM + c];
    outT[(long long)n * CDIM + c] = tf32f(s * (1.0f / (float)KDEG));
}

__global__ void agg_max_kernel(const float* __restrict__ x,
                               const int* __restrict__ src,
                               float* __restrict__ outT)
{
    int n = blockIdx.x;
    int c = threadIdx.x;
    __shared__ int sidx[KDEG];
    if (c < KDEG) sidx[c] = src[n * KDEG + c];
    __syncthreads();
    float m = -INFINITY;
    #pragma unroll
    for (int k = 0; k < KDEG; ++k)
        m = fmaxf(m, x[(long long)sidx[k] * CDIM + c]);
    outT[(long long)n * CDIM + c] = tf32f(m);
}

// ------------------------- JK attention + output ------------------------------
__global__ void jk_att_kernel(const float* __restrict__ h1,
                              const float* __restrict__ h2,
                              const float* __restrict__ h3,
                              const float* __restrict__ fwd0,
                              const float* __restrict__ fwd1,
                              const float* __restrict__ fwd2,
                              const float* __restrict__ bwd0,
                              const float* __restrict__ bwd1,
                              const float* __restrict__ bwd2,
                              const float* __restrict__ attw,
                              const float* __restrict__ attb,
                              float* __restrict__ out)
{
    int n = blockIdx.x;
    int tid = threadIdx.x;                 // 128
    const float* fw[3] = { fwd0, fwd1, fwd2 };
    const float* bw[3] = { bwd2, bwd1, bwd0 };   // bwd[::-1]

    __shared__ float red[128];
    __shared__ float sc[3];
    __shared__ float w[3];

    for (int t = 0; t < 3; ++t) {
        float p = 0.f;
        for (int j = tid; j < JKH; j += 128)
            p += fw[t][(long long)n * JKH + j] * attw[j]
               + bw[t][(long long)n * JKH + j] * attw[JKH + j];
        red[tid] = p;
        __syncthreads();
        for (int s = 64; s > 0; s >>= 1) {
            if (tid < s) red[tid] += red[tid + s];
            __syncthreads();
        }
        if (tid == 0) sc[t] = red[0] + attb[0];
        __syncthreads();
    }
    if (tid == 0) {
        float m = fmaxf(sc[0], fmaxf(sc[1], sc[2]));
        float e0 = expf(sc[0] - m), e1 = expf(sc[1] - m), e2 = expf(sc[2] - m);
        float s = e0 + e1 + e2;
        w[0] = e0 / s; w[1] = e1 / s; w[2] = e2 / s;
    }
    __syncthreads();
    long long o = (long long)n * CDIM + tid;
    out[o] = w[0] * h1[o] + w[1] * h2[o] + w[2] * h3[o];
}

// ------------------------- host driver ----------------------------------------
static void launch_gemm(int M, int Nout, int K1, int K2,
                        const float* A1, const int* gidx, int gstride, int goff,
                        const float* A2,
                        const float* W1, const float* W2,
                        const float* b1, const float* b2,
                        float* C, float* CT, int act)
{
    dim3 grid(Nout / BN, (M + BM - 1) / BM);
    gemm_tf32<<<grid, 256>>>(M, Nout, K1, K2, A1, gidx, gstride, goff,
                             A2, W1, W2, b1, b2, C, CT, act);
}

// single-chain LSTM step with precomputed XW (aggregation chain)
static void launch_lstm_step_xw(int M, int H,
                                const float* XW, const int* gidx, int gstride, int goff,
                                const float* hprev,
                                const float* Whh,
                                const float* bih, const float* bhh,
                                float* c, float* hout, float* houtT, int zero_c)
{
    dim3 grid(H / 16, (M + BM - 1) / BM, 1);
    gemm_lstm_tf32<<<grid, 256>>>(M, H, 0,
                                  nullptr, nullptr, XW, XW,
                                  gidx, gstride, goff,
                                  hprev, hprev,
                                  nullptr, Whh, bih, bhh,
                                  nullptr, Whh, bih, bhh,
                                  c, c, hout, hout, houtT, houtT, zero_c);
}

// dual-chain LSTM step (grid.z = 2): JK fwd (set 0) + bwd (set 1)
static void launch_lstm_step2(int M, int H, int K1,
                              const float* X0, const float* hp0,
                              const float* Wih0, const float* Whh0,
                              const float* bih0, const float* bhh0,
                              float* c0, float* ho0, float* hoT0,
                              const float* X1, const float* hp1,
                              const float* Wih1, const float* Whh1,
                              const float* bih1, const float* bhh1,
                              float* c1, float* ho1, float* hoT1,
                              int zero_c)
{
    dim3 grid(H / 16, (M + BM - 1) / BM, 2);
    gemm_lstm_tf32<<<grid, 256>>>(M, H, K1,
                                  X0, X1, nullptr, nullptr,
                                  nullptr, 0, 0,
                                  hp0, hp1,
                                  Wih0, Whh0, bih0, bhh0,
                                  Wih1, Whh1, bih1, bhh1,
                                  c0, c1, ho0, ho1, hoT0, hoT1, zero_c);
}

extern "C" void kernel_launch(void* const* d_in, const int* in_sizes, int n_in,
                              void* d_out, int out_size)
{
    int epos = -1;
    for (int i = 0; i < n_in; ++i)
        if (in_sizes[i] == 2 * E_EDGES) { epos = i; break; }

    const float* P[24];
    int q = 0;
    for (int i = 0; i < n_in && q < 24; ++i) {
        if (i == epos) continue;
        P[q++] = (const float*)d_in[i];
    }
    const float* x     = P[0];
    const float* Wl1   = P[1];  const float* bl1  = P[2];  const float* Wr1 = P[3];
    const float* Wl2   = P[4];  const float* bl2  = P[5];  const float* Wr2 = P[6];
    const float* Wl3   = P[7];  const float* bl3  = P[8];  const float* Wr3 = P[9];
    const float* Wih_a = P[10]; const float* Whh_a = P[11];
    const float* bih_a = P[12]; const float* bhh_a = P[13];
    const float* Wih_f = P[14]; const float* Whh_f = P[15];
    const float* bih_f = P[16]; const float* bhh_f = P[17];
    const float* Wih_b = P[18]; const float* Whh_b = P[19];
    const float* bih_b = P[20]; const float* bhh_b = P[21];
    const float* att_w = P[22]; const float* att_b = P[23];
    const void* edge_raw = d_in[epos];

    float *aggT, *h1, *h1T, *h2, *h2T, *h3, *h3T, *hAT, *cA, *xw;
    float *fwd, *fwdT, *bwd, *bwdT, *cf, *cb, *xT, *wT;
    int* src;
    cudaGetSymbolAddress((void**)&aggT, g_aggT);
    cudaGetSymbolAddress((void**)&h1,  g_h1);
    cudaGetSymbolAddress((void**)&h1T, g_h1T);
    cudaGetSymbolAddress((void**)&h2,  g_h2);
    cudaGetSymbolAddress((void**)&h2T, g_h2T);
    cudaGetSymbolAddress((void**)&h3,  g_h3);
    cudaGetSymbolAddress((void**)&h3T, g_h3T);
    cudaGetSymbolAddress((void**)&hAT, g_hAT);
    cudaGetSymbolAddress((void**)&cA,  g_cA);
    cudaGetSymbolAddress((void**)&xw,  g_xw);
    cudaGetSymbolAddress((void**)&fwd,  g_fwd);
    cudaGetSymbolAddress((void**)&fwdT, g_fwdT);
    cudaGetSymbolAddress((void**)&bwd,  g_bwd);
    cudaGetSymbolAddress((void**)&bwdT, g_bwdT);
    cudaGetSymbolAddress((void**)&cf,  g_cf);
    cudaGetSymbolAddress((void**)&cb,  g_cb);
    cudaGetSymbolAddress((void**)&xT,  g_xT);
    cudaGetSymbolAddress((void**)&wT,  g_wT);
    cudaGetSymbolAddress((void**)&src, g_src32);

    // weight scratch offsets (tf32 copies)
    float* Wl1T  = wT;            float* Wr1T  = wT + 16384;
    float* Wl2T  = wT + 32768;    float* Wr2T  = wT + 49152;
    float* Wl3T  = wT + 65536;    float* Wr3T  = wT + 81920;
    float* WihaT = wT + 98304;    float* WhhaT = wT + 163840;
    float* WihfT = wT + 229376;   float* WhhfT = wT + 327680;
    float* WihbT = wT + 475136;   float* WhhbT = wT + 573440;

    float* out = (float*)d_out;
    const int N = N_NODES;

    // ---- one-shot conversions ----
    detect_kernel<<<1, 1>>>(edge_raw);
    s32_convert<<<(E_EDGES + 255) / 256, 256>>>(edge_raw, src);
    cvt_arr<<<(N * CDIM + 255) / 256, 256>>>(x, xT, N * CDIM);
    {
        CvtJobs J;
        const float* ins[NCVT]  = { Wl1, Wr1, Wl2, Wr2, Wl3, Wr3,
                                    Wih_a, Whh_a, Wih_f, Whh_f, Wih_b, Whh_b };
        float* outs[NCVT] = { Wl1T, Wr1T, Wl2T, Wr2T, Wl3T, Wr3T,
                              WihaT, WhhaT, WihfT, WhhfT, WihbT, WhhbT };
        int ns[NCVT] = { 16384, 16384, 16384, 16384, 16384, 16384,
                         4 * CDIM * CDIM, 4 * CDIM * CDIM,
                         4 * JKH * CDIM, 4 * JKH * JKH,
                         4 * JKH * CDIM, 4 * JKH * JKH };
        for (int j = 0; j < NCVT; ++j) { J.in[j] = ins[j]; J.out[j] = outs[j]; J.n[j] = ns[j]; }
        dim3 g(576, NCVT);
        cvt_multi<<<g, 256>>>(J);
    }

    // ---- layer 1: mean agg + linear + relu ----
    agg_mean_kernel<<<N, CDIM>>>(x, src, aggT);
    launch_gemm(N, CDIM, CDIM, CDIM, aggT, nullptr, 0, 0, xT,
                Wl1T, Wr1T, bl1, nullptr, h1, h1T, 1);

    // ---- layer 2: max agg + linear + relu ----
    agg_max_kernel<<<N, CDIM>>>(h1, src, aggT);
    launch_gemm(N, CDIM, CDIM, CDIM, aggT, nullptr, 0, 0, h1T,
                Wl2T, Wr2T, bl2, nullptr, h2, h2T, 1);

    // ---- layer 3: LSTM aggregation ----
    // XW = h2T @ Wih_a^T (no bias), computed once; steps reuse it via gather.
    launch_gemm(N, 4 * CDIM, CDIM, 0, h2T, nullptr, 0, 0, nullptr,
                WihaT, nullptr, nullptr, nullptr, xw, nullptr, 0);
    for (int step = 0; step < KDEG; ++step) {
        const float* hprev = (step == 0) ? nullptr : hAT;
        launch_lstm_step_xw(N, CDIM,
                            xw, src, KDEG, step,
                            hprev, WhhaT, bih_a, bhh_a,
                            cA, nullptr, hAT, step == 0);
    }
    launch_gemm(N, CDIM, CDIM, CDIM, hAT, nullptr, 0, 0, h2T,
                Wl3T, Wr3T, bl3, nullptr, h3, h3T, 0);

    // ---- JumpingKnowledge bi-LSTM: fwd+bwd merged per step ----
    {
        const float* hsT[3] = { h1T, h2T, h3T };
        const float* hpF = nullptr;
        const float* hpB = nullptr;
        for (int t = 0; t < 3; ++t) {
            float* hoF  = fwd  + (size_t)t * N * JKH;
            float* hoFT = fwdT + (size_t)t * N * JKH;
            float* hoB  = bwd  + (size_t)t * N * JKH;
            float* hoBT = bwdT + (size_t)t * N * JKH;
            launch_lstm_step2(N, JKH, CDIM,
                              hsT[t],     hpF, WihfT, WhhfT, bih_f, bhh_f,
                              cf, hoF, hoFT,
                              hsT[2 - t], hpB, WihbT, WhhbT, bih_b, bhh_b,
                              cb, hoB, hoBT,
                              t == 0);
            hpF = hoFT;
            hpB = hoBT;
        }
        jk_att_kernel<<<N, CDIM>>>(h1, h2, h3,
                                   fwd, fwd + (size_t)N * JKH, fwd + (size_t)2 * N * JKH,
                                   bwd, bwd + (size_t)N * JKH, bwd + (size_t)2 * N * JKH,
                                   att_w, att_b, out);
    }
}

// round 16
// speedup vs baseline: 1.0614x; 1.0008x over previous
#include <cuda_runtime.h>
#include <cuda_bf16.h>
#include <math.h>

// ---------------------------------------------------------------------------
// GraphSAGE (mean -> max -> lstm aggr) + JumpingKnowledge bi-LSTM attention
// N=50000, K=16, C=128, JK_H=192
// Round 16: single tf32-valued activation buffers (no fp32/tf32 dual writes);
//   detect merged into s32; xT folded into cvt_multi so ncu capture (launch
//   index 3) lands on the layer-1 GEMM. Fast activations kept from R15.
// ---------------------------------------------------------------------------

#define N_NODES 50000
#define KDEG    16
#define CDIM    128
#define JKH     192
#define E_EDGES (N_NODES * KDEG)

// ------------------------- scratch (static device globals) ------------------
__device__ float g_aggT[N_NODES * CDIM];
__device__ float g_h1 [N_NODES * CDIM];      // tf32-valued
__device__ float g_h2 [N_NODES * CDIM];      // tf32-valued
__device__ float g_h3 [N_NODES * CDIM];      // tf32-valued
__device__ float g_hA [N_NODES * CDIM];      // tf32-valued
__device__ float g_cA [N_NODES * CDIM];
__device__ float g_xw [N_NODES * 4 * CDIM];  // XW = h2 @ Wih_a^T (fp32)
__device__ float g_fwd [3][N_NODES * JKH];   // tf32-valued
__device__ float g_bwd [3][N_NODES * JKH];   // tf32-valued
__device__ float g_cf [N_NODES * JKH];
__device__ float g_cb [N_NODES * JKH];
__device__ float g_xT [N_NODES * CDIM];
__device__ float g_wT [720896];
__device__ int   g_src32[E_EDGES];

// ------------------------- small helpers -------------------------------------
__device__ __forceinline__ unsigned cvt_tf32(float x)
{
    unsigned r;
    asm("cvt.rna.tf32.f32 %0, %1;" : "=r"(r) : "f"(x));
    return r;
}
__device__ __forceinline__ float tf32f(float x)
{
    return __uint_as_float(cvt_tf32(x));
}
__device__ __forceinline__ void mma_tf32(float* c,
                                         unsigned a0, unsigned a1,
                                         unsigned a2, unsigned a3,
                                         unsigned b0, unsigned b1)
{
    asm volatile(
        "mma.sync.aligned.m16n8k8.row.col.f32.tf32.tf32.f32 "
        "{%0,%1,%2,%3}, {%4,%5,%6,%7}, {%8,%9}, {%0,%1,%2,%3};\n"
        : "+f"(c[0]), "+f"(c[1]), "+f"(c[2]), "+f"(c[3])
        : "r"(a0), "r"(a1), "r"(a2), "r"(a3), "r"(b0), "r"(b1));
}
// Fast activations: MUFU EX2/RCP based, ~2 ulp — negligible vs tf32 floor.
__device__ __forceinline__ float sigf(float x)
{
    return __fdividef(1.f, 1.f + __expf(-x));
}
__device__ __forceinline__ float tanhff(float x)
{
    return __fdividef(2.f, 1.f + __expf(-2.f * x)) - 1.f;
}

__device__ __forceinline__ unsigned s2u(const void* p)
{
    unsigned a;
    asm("{.reg .u64 t; cvta.to.shared.u64 t, %1; cvt.u32.u64 %0, t;}"
        : "=r"(a) : "l"(p));
    return a;
}
__device__ __forceinline__ void cp16(unsigned d, const void* s, int sz)
{
    asm volatile("cp.async.cg.shared.global [%0], [%1], 16, %2;\n"
                 :: "r"(d), "l"(s), "r"(sz));
}
#define CP_COMMIT() asm volatile("cp.async.commit_group;\n")
#define CP_WAIT0()  asm volatile("cp.async.wait_group 0;\n")

// ------------------------- dtype detect + convert (merged) --------------------
// Per-block probe: thread 0 checks the first 256 entries under the int64
// interpretation; all in [0,N) -> int64 layout, else int32.
__global__ void s32d(const void* __restrict__ p, int* __restrict__ src32)
{
    __shared__ int ok;
    if (threadIdx.x == 0) {
        const long long* a = (const long long*)p;
        int r = 1;
        for (int i = 0; i < 256; ++i) {
            long long v = a[i];
            if (v < 0 || v >= N_NODES) { r = 0; break; }
        }
        ok = r;
    }
    __syncthreads();
    int i = blockIdx.x * blockDim.x + threadIdx.x;
    if (i >= E_EDGES) return;
    src32[i] = ok ? (int)((const long long*)p)[i] : ((const int*)p)[i];
}

#define NCVT 13
struct CvtJobs {
    const float* in[NCVT];
    float*       out[NCVT];
    int          n[NCVT];
};
__global__ void cvt_multi(CvtJobs J)
{
    int j = blockIdx.y;
    int n = J.n[j];
    const float* in = J.in[j];
    float* out = J.out[j];
    for (int i = blockIdx.x * blockDim.x + threadIdx.x; i < n;
         i += gridDim.x * blockDim.x)
        out[i] = tf32f(in[i]);
}

// ------------------------- tiling constants -----------------------------------
#define BM 128
#define BN 64
#define BK 32
#define SA_STAGE (BM * 32)          // 4096 floats
#define SB_STAGE (BN * 32)          // 2048 floats

__device__ __forceinline__ float lds_sw(const float* s, int r, int kc)
{
    return s[r * 32 + (((kc >> 2) ^ (r & 7)) << 2) + (kc & 3)];
}

// ------------------------- plain dual tf32 GEMM -------------------------------
// C[M,Nout] = A1@W1^T + A2@W2^T + b1 + b2 (+relu). All A/W pre-tf32.
// round_out: round stored values to tf32 (activation buffers) or keep fp32 (XW).
__global__ __launch_bounds__(256)
void gemm_tf32(int M, int Nout, int K1, int K2,
               const float* __restrict__ A1,
               const int* __restrict__ gidx, int gstride, int goff,
               const float* __restrict__ A2,
               const float* __restrict__ W1, const float* __restrict__ W2,
               const float* __restrict__ b1, const float* __restrict__ b2,
               float* __restrict__ Cout, int act, int round_out)
{
    __shared__ float smem_all[2 * SA_STAGE + 2 * SB_STAGE];

    const int tid  = threadIdx.x;
    const int lane = tid & 31;
    const int warp = tid >> 5;
    const int wm   = warp & 3;
    const int wn   = warp >> 2;
    const int mbase = blockIdx.y * BM;
    const int nbase = blockIdx.x * BN;
    const int lq = lane >> 2;
    const int lr = lane & 3;

    int rg[4];
    #pragma unroll
    for (int p = 0; p < 4; ++p) {
        int grow = mbase + ((tid + p * 256) >> 3);
        rg[p] = (grow < M) ? (gidx ? __ldg(&gidx[grow * gstride + goff]) : grow) : 0;
    }

    float acc[2][4][4];
    #pragma unroll
    for (int mt = 0; mt < 2; ++mt)
        #pragma unroll
        for (int nt = 0; nt < 4; ++nt)
            #pragma unroll
            for (int f = 0; f < 4; ++f) acc[mt][nt][f] = 0.f;

    const int Ktot = (A2 == nullptr) ? K1 : (K1 + K2);
    const int T = Ktot / BK;

    auto stage = [&](int t, int s) {
        int kt = t * BK;
        bool seg2 = (kt >= K1);
        const float* A = seg2 ? A2 : A1;
        const float* W = seg2 ? W2 : W1;
        int K    = seg2 ? K2 : K1;
        int kloc = seg2 ? kt - K1 : kt;
        float* sa = smem_all + s * SA_STAGE;
        float* sb = smem_all + 2 * SA_STAGE + s * SB_STAGE;
        #pragma unroll
        for (int p = 0; p < 4; ++p) {
            int lin = tid + p * 256;
            int row = lin >> 3, kf4 = lin & 7;
            int grow = mbase + row;
            bool ok = grow < M;
            int r = seg2 ? (ok ? grow : 0) : rg[p];
            unsigned d = s2u(sa + row * 32 + ((kf4 ^ (row & 7)) << 2));
            cp16(d, A + (size_t)r * K + kloc + kf4 * 4, ok ? 16 : 0);
        }
        #pragma unroll
        for (int p = 0; p < 2; ++p) {
            int lin = tid + p * 256;
            int n = lin >> 3, kf4 = lin & 7;
            unsigned d = s2u(sb + n * 32 + ((kf4 ^ (n & 7)) << 2));
            cp16(d, W + (size_t)(nbase + n) * K + kloc + kf4 * 4, 16);
        }
        CP_COMMIT();
    };

    stage(0, 0);

    for (int t = 0; t < T; ++t) {
        int cur = t & 1;
        CP_WAIT0();
        __syncthreads();
        if (t + 1 < T) stage(t + 1, cur ^ 1);

        const float* sa = smem_all + cur * SA_STAGE;
        const float* sb = smem_all + 2 * SA_STAGE + cur * SB_STAGE;
        #pragma unroll
        for (int ks = 0; ks < 4; ++ks) {
            const int kc = ks * 8 + lr;
            unsigned bfr[4][2];
            #pragma unroll
            for (int nt = 0; nt < 4; ++nt) {
                int n = wn * 32 + nt * 8 + lq;
                bfr[nt][0] = __float_as_uint(lds_sw(sb, n, kc));
                bfr[nt][1] = __float_as_uint(lds_sw(sb, n, kc + 4));
            }
            #pragma unroll
            for (int mt = 0; mt < 2; ++mt) {
                int r = wm * 32 + mt * 16 + lq;
                unsigned a0 = __float_as_uint(lds_sw(sa, r, kc));
                unsigned a1 = __float_as_uint(lds_sw(sa, r + 8, kc));
                unsigned a2 = __float_as_uint(lds_sw(sa, r, kc + 4));
                unsigned a3 = __float_as_uint(lds_sw(sa, r + 8, kc + 4));
                #pragma unroll
                for (int nt = 0; nt < 4; ++nt)
                    mma_tf32(acc[mt][nt], a0, a1, a2, a3, bfr[nt][0], bfr[nt][1]);
            }
        }
        __syncthreads();
    }

    #pragma unroll
    for (int mt = 0; mt < 2; ++mt) {
        #pragma unroll
        for (int nt = 0; nt < 4; ++nt) {
            int col  = nbase + wn * 32 + nt * 8 + 2 * lr;
            float bias0 = (b1 ? b1[col]     : 0.f) + (b2 ? b2[col]     : 0.f);
            float bias1 = (b1 ? b1[col + 1] : 0.f) + (b2 ? b2[col + 1] : 0.f);
            int row0 = mbase + wm * 32 + mt * 16 + lq;
            float v0 = acc[mt][nt][0] + bias0;
            float v1 = acc[mt][nt][1] + bias1;
            float v2 = acc[mt][nt][2] + bias0;
            float v3 = acc[mt][nt][3] + bias1;
            if (act) {
                v0 = fmaxf(v0, 0.f); v1 = fmaxf(v1, 0.f);
                v2 = fmaxf(v2, 0.f); v3 = fmaxf(v3, 0.f);
            }
            if (round_out) {
                v0 = tf32f(v0); v1 = tf32f(v1);
                v2 = tf32f(v2); v3 = tf32f(v3);
            }
            if (row0 < M) {
                size_t o = (size_t)row0 * Nout + col;
                Cout[o] = v0; Cout[o + 1] = v1;
            }
            if (row0 + 8 < M) {
                size_t o = (size_t)(row0 + 8) * Nout + col;
                Cout[o] = v2; Cout[o + 1] = v3;
            }
        }
    }
}

// ------------------------- fused LSTM-step GEMM (dual-chain + XW) -------------
// blockIdx.z selects parameter set 0/1. If XW != nullptr: z = XW[gidx[...]] +
// h_prev@Whh^T + bias (x-part precomputed). Else z = [x_t;h_prev]@[Wih;Whh]^T
// + bias. hprev==nullptr -> first step. Writes tf32-valued h only.
__global__ __launch_bounds__(256)
void gemm_lstm_tf32(int M, int H, int K1,
                    const float* __restrict__ X0, const float* __restrict__ X1,
                    const float* __restrict__ XW0, const float* __restrict__ XW1,
                    const int* __restrict__ gidx, int gstride, int goff,
                    const float* __restrict__ hprev0, const float* __restrict__ hprev1,
                    const float* __restrict__ Wih0, const float* __restrict__ Whh0,
                    const float* __restrict__ bih0, const float* __restrict__ bhh0,
                    const float* __restrict__ Wih1, const float* __restrict__ Whh1,
                    const float* __restrict__ bih1, const float* __restrict__ bhh1,
                    float* __restrict__ cst0, float* __restrict__ cst1,
                    float* __restrict__ hout0, float* __restrict__ hout1,
                    int zero_c)
{
    __shared__ float smem_all[2 * SA_STAGE + 2 * SB_STAGE];

    const int zsel = blockIdx.z;
    const float* X     = zsel ? X1     : X0;
    const float* XW    = zsel ? XW1    : XW0;
    const float* hprev = zsel ? hprev1 : hprev0;
    const float* Wih   = zsel ? Wih1   : Wih0;
    const float* Whh   = zsel ? Whh1   : Whh0;
    const float* bih   = zsel ? bih1   : bih0;
    const float* bhh   = zsel ? bhh1   : bhh0;
    float* cst  = zsel ? cst1  : cst0;
    float* hout = zsel ? hout1 : hout0;

    const int tid  = threadIdx.x;
    const int lane = tid & 31;
    const int warp = tid >> 5;
    const int wm   = warp & 3;
    const int wn   = warp >> 2;
    const int mbase = blockIdx.y * BM;
    const int cbase = blockIdx.x * 16;
    const int lq = lane >> 2;
    const int lr = lane & 3;

    const bool use_xw = (XW != nullptr);
    const int KX = use_xw ? 0 : K1;

    int rg[4];
    if (!use_xw) {
        #pragma unroll
        for (int p = 0; p < 4; ++p) {
            int grow = mbase + ((tid + p * 256) >> 3);
            rg[p] = (grow < M) ? (gidx ? __ldg(&gidx[grow * gstride + goff]) : grow) : 0;
        }
    }

    float acc[2][4][4];
    #pragma unroll
    for (int mt = 0; mt < 2; ++mt)
        #pragma unroll
        for (int nt = 0; nt < 4; ++nt)
            #pragma unroll
            for (int f = 0; f < 4; ++f) acc[mt][nt][f] = 0.f;

    const int Ktot = KX + ((hprev != nullptr) ? H : 0);
    const int T = Ktot / BK;

    auto stage = [&](int t, int s) {
        int kt = t * BK;
        bool seg2 = (kt >= KX);
        const float* A = seg2 ? hprev : X;
        const float* W = seg2 ? Whh : Wih;
        int K    = seg2 ? H : K1;
        int kloc = seg2 ? kt - KX : kt;
        float* sa = smem_all + s * SA_STAGE;
        float* sb = smem_all + 2 * SA_STAGE + s * SB_STAGE;
        #pragma unroll
        for (int p = 0; p < 4; ++p) {
            int lin = tid + p * 256;
            int row = lin >> 3, kf4 = lin & 7;
            int grow = mbase + row;
            bool ok = grow < M;
            int r = seg2 ? (ok ? grow : 0) : rg[p];
            unsigned d = s2u(sa + row * 32 + ((kf4 ^ (row & 7)) << 2));
            cp16(d, A + (size_t)r * K + kloc + kf4 * 4, ok ? 16 : 0);
        }
        #pragma unroll
        for (int p = 0; p < 2; ++p) {
            int lin = tid + p * 256;
            int n = lin >> 3, kf4 = lin & 7;
            int wrow = (n >> 4) * H + cbase + (n & 15);   // gate-major W rows
            unsigned d = s2u(sb + n * 32 + ((kf4 ^ (n & 7)) << 2));
            cp16(d, W + (size_t)wrow * K + kloc + kf4 * 4, 16);
        }
        CP_COMMIT();
    };

    if (T > 0) stage(0, 0);

    for (int t = 0; t < T; ++t) {
        int cur = t & 1;
        CP_WAIT0();
        __syncthreads();
        if (t + 1 < T) stage(t + 1, cur ^ 1);

        const float* sa = smem_all + cur * SA_STAGE;
        const float* sb = smem_all + 2 * SA_STAGE + cur * SB_STAGE;
        #pragma unroll
        for (int ks = 0; ks < 4; ++ks) {
            const int kc = ks * 8 + lr;
            unsigned bfr[4][2];
            #pragma unroll
            for (int nt = 0; nt < 4; ++nt) {
                int n = nt * 16 + wn * 8 + lq;        // gate nt
                bfr[nt][0] = __float_as_uint(lds_sw(sb, n, kc));
                bfr[nt][1] = __float_as_uint(lds_sw(sb, n, kc + 4));
            }
            #pragma unroll
            for (int mt = 0; mt < 2; ++mt) {
                int r = wm * 32 + mt * 16 + lq;
                unsigned a0 = __float_as_uint(lds_sw(sa, r, kc));
                unsigned a1 = __float_as_uint(lds_sw(sa, r + 8, kc));
                unsigned a2 = __float_as_uint(lds_sw(sa, r, kc + 4));
                unsigned a3 = __float_as_uint(lds_sw(sa, r + 8, kc + 4));
                #pragma unroll
                for (int nt = 0; nt < 4; ++nt)
                    mma_tf32(acc[mt][nt], a0, a1, a2, a3, bfr[nt][0], bfr[nt][1]);
            }
        }
        __syncthreads();
    }

    // ---- fused LSTM epilogue (+ optional XW gather) ----
    const int cl0 = wn * 8 + 2 * lr;
    float bI[2], bF[2], bG[2], bO[2];
    #pragma unroll
    for (int cc = 0; cc < 2; ++cc) {
        int col = cbase + cl0 + cc;
        bI[cc] = bih[0 * H + col] + bhh[0 * H + col];
        bF[cc] = bih[1 * H + col] + bhh[1 * H + col];
        bG[cc] = bih[2 * H + col] + bhh[2 * H + col];
        bO[cc] = bih[3 * H + col] + bhh[3 * H + col];
    }

    #pragma unroll
    for (int mt = 0; mt < 2; ++mt) {
        int row0 = mbase + wm * 32 + mt * 16 + lq;
        #pragma unroll
        for (int p = 0; p < 2; ++p) {
            int row = row0 + p * 8;
            if (row >= M) continue;

            float2 xw[4];
            #pragma unroll
            for (int g = 0; g < 4; ++g) xw[g] = make_float2(0.f, 0.f);
            if (use_xw) {
                int sr = __ldg(&gidx[row * gstride + goff]);
                const float* xr = XW + (size_t)sr * (4 * H) + cbase + cl0;
                #pragma unroll
                for (int g = 0; g < 4; ++g)
                    xw[g] = __ldg((const float2*)(xr + g * H));
            }

            #pragma unroll
            for (int cc = 0; cc < 2; ++cc) {
                int f = p * 2 + cc;
                int col = cbase + cl0 + cc;
                float zi = acc[mt][0][f] + bI[cc] + (cc ? xw[0].y : xw[0].x);
                float zf = acc[mt][1][f] + bF[cc] + (cc ? xw[1].y : xw[1].x);
                float zg = acc[mt][2][f] + bG[cc] + (cc ? xw[2].y : xw[2].x);
                float zo = acc[mt][3][f] + bO[cc] + (cc ? xw[3].y : xw[3].x);
                float ig = sigf(zi), fg = sigf(zf);
                float gg = tanhff(zg), og = sigf(zo);
                size_t idx = (size_t)row * H + col;
                float cp = zero_c ? 0.f : cst[idx];
                float cn = fg * cp + ig * gg;
                cst[idx] = cn;
                hout[idx] = tf32f(og * tanhff(cn));
            }
        }
    }
}

// ------------------------- aggregation kernels (tf32 outputs) -----------------
__global__ void agg_mean_kernel(const float* __restrict__ x,
                                const int* __restrict__ src,
                                float* __restrict__ outT)
{
    int n = blockIdx.x;
    int c = threadIdx.x;
    __shared__ int sidx[KDEG];
    if (c < KDEG) sidx[c] = src[n * KDEG + c];
    __syncthreads();
    float s = 0.f;
    #pragma unroll
    for (int k = 0; k < KDEG; ++k)
        s += x[(long long)sidx[k] * CDIM + c];
    outT[(long long)n * CDIM + c] = tf32f(s * (1.0f / (float)KDEG));
}

__global__ void agg_max_kernel(const float* __restrict__ x,
                               const int* __restrict__ src,
                               float* __restrict__ outT)
{
    int n = blockIdx.x;
    int c = threadIdx.x;
    __shared__ int sidx[KDEG];
    if (c < KDEG) sidx[c] = src[n * KDEG + c];
    __syncthreads();
    float m = -INFINITY;
    #pragma unroll
    for (int k = 0; k < KDEG; ++k)
        m = fmaxf(m, x[(long long)sidx[k] * CDIM + c]);
    outT[(long long)n * CDIM + c] = tf32f(m);
}

// ------------------------- JK attention + output ------------------------------
__global__ void jk_att_kernel(const float* __restrict__ h1,
                              const float* __restrict__ h2,
                              const float* __restrict__ h3,
                              const float* __restrict__ fwd0,
                              const float* __restrict__ fwd1,
                              const float* __restrict__ fwd2,
                              const float* __restrict__ bwd0,
                              const float* __restrict__ bwd1,
                              const float* __restrict__ bwd2,
                              const float* __restrict__ attw,
                              const float* __restrict__ attb,
                              float* __restrict__ out)
{
    int n = blockIdx.x;
    int tid = threadIdx.x;                 // 128
    const float* fw[3] = { fwd0, fwd1, fwd2 };
    const float* bw[3] = { bwd2, bwd1, bwd0 };   // bwd[::-1]

    __shared__ float red[128];
    __shared__ float sc[3];
    __shared__ float w[3];

    for (int t = 0; t < 3; ++t) {
        float p = 0.f;
        for (int j = tid; j < JKH; j += 128)
            p += fw[t][(long long)n * JKH + j] * attw[j]
               + bw[t][(long long)n * JKH + j] * attw[JKH + j];
        red[tid] = p;
        __syncthreads();
        for (int s = 64; s > 0; s >>= 1) {
            if (tid < s) red[tid] += red[tid + s];
            __syncthreads();
        }
        if (tid == 0) sc[t] = red[0] + attb[0];
        __syncthreads();
    }
    if (tid == 0) {
        float m = fmaxf(sc[0], fmaxf(sc[1], sc[2]));
        float e0 = expf(sc[0] - m), e1 = expf(sc[1] - m), e2 = expf(sc[2] - m);
        float s = e0 + e1 + e2;
        w[0] = e0 / s; w[1] = e1 / s; w[2] = e2 / s;
    }
    __syncthreads();
    long long o = (long long)n * CDIM + tid;
    out[o] = w[0] * h1[o] + w[1] * h2[o] + w[2] * h3[o];
}

// ------------------------- host driver ----------------------------------------
static void launch_gemm(int M, int Nout, int K1, int K2,
                        const float* A1, const int* gidx, int gstride, int goff,
                        const float* A2,
                        const float* W1, const float* W2,
                        const float* b1, const float* b2,
                        float* C, int act, int round_out)
{
    dim3 grid(Nout / BN, (M + BM - 1) / BM);
    gemm_tf32<<<grid, 256>>>(M, Nout, K1, K2, A1, gidx, gstride, goff,
                             A2, W1, W2, b1, b2, C, act, round_out);
}

// single-chain LSTM step with precomputed XW (aggregation chain)
static void launch_lstm_step_xw(int M, int H,
                                const float* XW, const int* gidx, int gstride, int goff,
                                const float* hprev,
                                const float* Whh,
                                const float* bih, const float* bhh,
                                float* c, float* hout, int zero_c)
{
    dim3 grid(H / 16, (M + BM - 1) / BM, 1);
    gemm_lstm_tf32<<<grid, 256>>>(M, H, 0,
                                  nullptr, nullptr, XW, XW,
                                  gidx, gstride, goff,
                                  hprev, hprev,
                                  nullptr, Whh, bih, bhh,
                                  nullptr, Whh, bih, bhh,
                                  c, c, hout, hout, zero_c);
}

// dual-chain LSTM step (grid.z = 2): JK fwd (set 0) + bwd (set 1)
static void launch_lstm_step2(int M, int H, int K1,
                              const float* X0, const float* hp0,
                              const float* Wih0, const float* Whh0,
                              const float* bih0, const float* bhh0,
                              float* c0, float* ho0,
                              const float* X1, const float* hp1,
                              const float* Wih1, const float* Whh1,
                              const float* bih1, const float* bhh1,
                              float* c1, float* ho1,
                              int zero_c)
{
    dim3 grid(H / 16, (M + BM - 1) / BM, 2);
    gemm_lstm_tf32<<<grid, 256>>>(M, H, K1,
                                  X0, X1, nullptr, nullptr,
                                  nullptr, 0, 0,
                                  hp0, hp1,
                                  Wih0, Whh0, bih0, bhh0,
                                  Wih1, Whh1, bih1, bhh1,
                                  c0, c1, ho0, ho1, zero_c);
}

extern "C" void kernel_launch(void* const* d_in, const int* in_sizes, int n_in,
                              void* d_out, int out_size)
{
    int epos = -1;
    for (int i = 0; i < n_in; ++i)
        if (in_sizes[i] == 2 * E_EDGES) { epos = i; break; }

    const float* P[24];
    int q = 0;
    for (int i = 0; i < n_in && q < 24; ++i) {
        if (i == epos) continue;
        P[q++] = (const float*)d_in[i];
    }
    const float* x     = P[0];
    const float* Wl1   = P[1];  const float* bl1  = P[2];  const float* Wr1 = P[3];
    const float* Wl2   = P[4];  const float* bl2  = P[5];  const float* Wr2 = P[6];
    const float* Wl3   = P[7];  const float* bl3  = P[8];  const float* Wr3 = P[9];
    const float* Wih_a = P[10]; const float* Whh_a = P[11];
    const float* bih_a = P[12]; const float* bhh_a = P[13];
    const float* Wih_f = P[14]; const float* Whh_f = P[15];
    const float* bih_f = P[16]; const float* bhh_f = P[17];
    const float* Wih_b = P[18]; const float* Whh_b = P[19];
    const float* bih_b = P[20]; const float* bhh_b = P[21];
    const float* att_w = P[22]; const float* att_b = P[23];
    const void* edge_raw = d_in[epos];

    float *aggT, *h1, *h2, *h3, *hA, *cA, *xw;
    float *fwd, *bwd, *cf, *cb, *xT, *wT;
    int* src;
    cudaGetSymbolAddress((void**)&aggT, g_aggT);
    cudaGetSymbolAddress((void**)&h1,  g_h1);
    cudaGetSymbolAddress((void**)&h2,  g_h2);
    cudaGetSymbolAddress((void**)&h3,  g_h3);
    cudaGetSymbolAddress((void**)&hA,  g_hA);
    cudaGetSymbolAddress((void**)&cA,  g_cA);
    cudaGetSymbolAddress((void**)&xw,  g_xw);
    cudaGetSymbolAddress((void**)&fwd, g_fwd);
    cudaGetSymbolAddress((void**)&bwd, g_bwd);
    cudaGetSymbolAddress((void**)&cf,  g_cf);
    cudaGetSymbolAddress((void**)&cb,  g_cb);
    cudaGetSymbolAddress((void**)&xT,  g_xT);
    cudaGetSymbolAddress((void**)&wT,  g_wT);
    cudaGetSymbolAddress((void**)&src, g_src32);

    // weight scratch offsets (tf32 copies)
    float* Wl1T  = wT;            float* Wr1T  = wT + 16384;
    float* Wl2T  = wT + 32768;    float* Wr2T  = wT + 49152;
    float* Wl3T  = wT + 65536;    float* Wr3T  = wT + 81920;
    float* WihaT = wT + 98304;    float* WhhaT = wT + 163840;
    float* WihfT = wT + 229376;   float* WhhfT = wT + 327680;
    float* WihbT = wT + 475136;   float* WhhbT = wT + 573440;

    float* out = (float*)d_out;
    const int N = N_NODES;

    // ---- launch 0: dtype detect + index convert (merged) ----
    s32d<<<(E_EDGES + 255) / 256, 256>>>(edge_raw, src);
    // ---- launch 1: mean aggregation ----
    agg_mean_kernel<<<N, CDIM>>>(x, src, aggT);
    // ---- launch 2: all tf32 conversions (x + 12 weights) ----
    {
        CvtJobs J;
        const float* ins[NCVT]  = { x, Wl1, Wr1, Wl2, Wr2, Wl3, Wr3,
                                    Wih_a, Whh_a, Wih_f, Whh_f, Wih_b, Whh_b };
        float* outs[NCVT] = { xT, Wl1T, Wr1T, Wl2T, Wr2T, Wl3T, Wr3T,
                              WihaT, WhhaT, WihfT, WhhfT, WihbT, WhhbT };
        int ns[NCVT] = { N_NODES * CDIM,
                         16384, 16384, 16384, 16384, 16384, 16384,
                         4 * CDIM * CDIM, 4 * CDIM * CDIM,
                         4 * JKH * CDIM, 4 * JKH * JKH,
                         4 * JKH * CDIM, 4 * JKH * JKH };
        for (int j = 0; j < NCVT; ++j) { J.in[j] = ins[j]; J.out[j] = outs[j]; J.n[j] = ns[j]; }
        dim3 g(576, NCVT);
        cvt_multi<<<g, 256>>>(J);
    }

    // ---- launch 3: layer-1 GEMM (ncu capture target) ----
    launch_gemm(N, CDIM, CDIM, CDIM, aggT, nullptr, 0, 0, xT,
                Wl1T, Wr1T, bl1, nullptr, h1, 1, 1);

    // ---- layer 2: max agg + linear + relu ----
    agg_max_kernel<<<N, CDIM>>>(h1, src, aggT);
    launch_gemm(N, CDIM, CDIM, CDIM, aggT, nullptr, 0, 0, h1,
                Wl2T, Wr2T, bl2, nullptr, h2, 1, 1);

    // ---- layer 3: LSTM aggregation ----
    launch_gemm(N, 4 * CDIM, CDIM, 0, h2, nullptr, 0, 0, nullptr,
                WihaT, nullptr, nullptr, nullptr, xw, 0, 0);   // XW fp32
    for (int step = 0; step < KDEG; ++step) {
        const float* hprev = (step == 0) ? nullptr : hA;
        launch_lstm_step_xw(N, CDIM,
                            xw, src, KDEG, step,
                            hprev, WhhaT, bih_a, bhh_a,
                            cA, hA, step == 0);
    }
    launch_gemm(N, CDIM, CDIM, CDIM, hA, nullptr, 0, 0, h2,
                Wl3T, Wr3T, bl3, nullptr, h3, 0, 1);

    // ---- JumpingKnowledge bi-LSTM: fwd+bwd merged per step ----
    {
        const float* hs[3] = { h1, h2, h3 };
        const float* hpF = nullptr;
        const float* hpB = nullptr;
        for (int t = 0; t < 3; ++t) {
            float* hoF = fwd + (size_t)t * N * JKH;
            float* hoB = bwd + (size_t)t * N * JKH;
            launch_lstm_step2(N, JKH, CDIM,
                              hs[t],     hpF, WihfT, WhhfT, bih_f, bhh_f,
                              cf, hoF,
                              hs[2 - t], hpB, WihbT, WhhbT, bih_b, bhh_b,
                              cb, hoB,
                              t == 0);
            hpF = hoF;
            hpB = hoB;
        }
        jk_att_kernel<<<N, CDIM>>>(h1, h2, h3,
                                   fwd, fwd + (size_t)N * JKH, fwd + (size_t)2 * N * JKH,
                                   bwd, bwd + (size_t)N * JKH, bwd + (size_t)2 * N * JKH,
                                   att_w, att_b, out);
    }
}